// round 1
// baseline (speedup 1.0000x reference)
#include <cuda_runtime.h>

// Problem constants
#define BB 4
#define CIN_X 64
#define COUT 128
#define DD 8
#define HH 128
#define WW 128
#define EE 256
#define OH 63
#define OW 63
#define HW (HH*WW)            // 16384
#define DHW (DD*HH*WW)        // 131072

// Scratch (device globals — allocation APIs are banned)
__device__ float g_s1[BB*CIN_X];                  // (4,64)
__device__ float g_s2[BB*COUT];                   // (4,128)
__device__ float g_act[BB*CIN_X*DHW];             // swish(x+s1)        134 MB
__device__ float g_h1[BB*COUT*DHW];               // after conv20 epi   268 MB
__device__ float g_h2[BB*COUT*DHW];               // after conv21 epi   268 MB

__device__ __forceinline__ float swish_f(float v) {
    return v / (1.f + __expf(-v));
}

// ---------------------------------------------------------------------------
// Kernel 1: s1 = embed @ d1_w + d1_b (4x64); s2 = context @ d2_w + d2_b (4x128)
// ---------------------------------------------------------------------------
__global__ void s_kernel(const float* __restrict__ embed,
                         const float* __restrict__ context,
                         const float* __restrict__ d1w, const float* __restrict__ d1b,
                         const float* __restrict__ d2w, const float* __restrict__ d2b)
{
    int t = threadIdx.x;   // 512 threads
    if (t < BB*CIN_X) {
        int n = t >> 6, c = t & 63;
        float acc = d1b[c];
        #pragma unroll 4
        for (int e = 0; e < EE; e++) acc += embed[n*EE + e] * d1w[e*CIN_X + c];
        g_s1[t] = acc;
    }
    {
        int n = t >> 7, c = t & 127;
        float acc = d2b[c];
        #pragma unroll 4
        for (int e = 0; e < EE; e++) acc += context[n*EE + e] * d2w[e*COUT + c];
        g_s2[t] = acc;
    }
}

// ---------------------------------------------------------------------------
// Kernel 2: g_act = swish(x + s1[n][ci]), vectorized float4
// ---------------------------------------------------------------------------
__global__ void act_kernel(const float* __restrict__ x)
{
    int idx4 = blockIdx.x * blockDim.x + threadIdx.x;       // 8388608 float4s
    int elem = idx4 << 2;
    int c = (elem >> 17) & 63;                               // DHW = 2^17
    int n = elem >> 23;                                      // 64*DHW = 2^23
    float s = g_s1[n*CIN_X + c];
    float4 v = ((const float4*)x)[idx4];
    float4 o;
    o.x = swish_f(v.x + s);
    o.y = swish_f(v.y + s);
    o.z = swish_f(v.z + s);
    o.w = swish_f(v.w + s);
    ((float4*)g_act)[idx4] = o;
}

// ---------------------------------------------------------------------------
// Kernel 3/4: 3x3x3 conv, stride 1, pad 1 on D/H/W.
// MODE 0: in = g_act (CIN=64),  epi: +b20, swish, *s2  -> g_h1
// MODE 1: in = g_h1 (CIN=128), + residual 1x1x1 conv(x)*res_w, +res_b, swish -> g_h2
// Block: one (n,d,h) output row, 64 output channels. Thread: 8 co x 4 w.
// ---------------------------------------------------------------------------
template<int CIN, int MODE>
__global__ void __launch_bounds__(256, 2) conv3x3_kernel(
    const float* __restrict__ wgt,    // (64|128-co-block via blockIdx.z) x CIN x 27
    const float* __restrict__ bias,   // b20 (MODE 0) or res_b (MODE 1)
    const float* __restrict__ xres,   // x (MODE 1 only)
    const float* __restrict__ resw)   // res_w (MODE 1 only), (COUT, 64)
{
    constexpr int CI_STEP = 2;
    __shared__ float sIn[CI_STEP*9*132];
    __shared__ float sW[CI_STEP*64*27];

    const float* in  = (MODE == 0) ? g_act : g_h1;
    float*       out = (MODE == 0) ? g_h1  : g_h2;

    const int h   = blockIdx.x;
    const int d   = blockIdx.y & 7;
    const int n   = blockIdx.y >> 3;
    const int cob = blockIdx.z << 6;
    const int tid = threadIdx.x;
    const int wg  = tid & 31;
    const int cg  = tid >> 5;
    const int w0  = wg << 2;

    float acc[8][4];
    #pragma unroll
    for (int i = 0; i < 8; i++)
        #pragma unroll
        for (int j = 0; j < 4; j++) acc[i][j] = 0.f;

    for (int ci0 = 0; ci0 < CIN; ci0 += CI_STEP) {
        __syncthreads();
        // stage input rows (3 kd planes x 3 kh rows x 130 w) per ci in chunk
        for (int i = tid; i < CI_STEP*9*130; i += 256) {
            int wi = i % 130;
            int r  = i / 130;
            int p  = r % 9;
            int c  = r / 9;
            int kd = p / 3, kh = p - kd*3;
            int id = d + kd - 1;
            int ih = h + kh - 1;
            int w  = wi - 1;
            float v = 0.f;
            if ((unsigned)id < (unsigned)DD && (unsigned)ih < (unsigned)HH &&
                (unsigned)w < (unsigned)WW)
                v = in[((n*CIN + ci0 + c)*DD + id)*HW + ih*WW + w];
            sIn[(c*9 + p)*132 + wi] = v;
        }
        // stage weights: 64 co x 27 per ci in chunk
        for (int i = tid; i < CI_STEP*64*27; i += 256) {
            int k   = i % 27;
            int r   = i / 27;
            int col = r & 63;
            int c   = r >> 6;
            sW[(c*64 + col)*27 + k] = wgt[((cob + col)*CIN + ci0 + c)*27 + k];
        }
        __syncthreads();

        #pragma unroll
        for (int c = 0; c < CI_STEP; c++) {
            #pragma unroll
            for (int p = 0; p < 9; p++) {
                const float* rp = &sIn[(c*9 + p)*132 + w0];
                float i0 = rp[0], i1 = rp[1], i2 = rp[2];
                float i3 = rp[3], i4 = rp[4], i5 = rp[5];
                const float* wp = &sW[(c*64 + (cg << 3))*27 + p*3];
                #pragma unroll
                for (int cr = 0; cr < 8; cr++) {
                    float wa = wp[cr*27 + 0];
                    float wb = wp[cr*27 + 1];
                    float wc = wp[cr*27 + 2];
                    acc[cr][0] = fmaf(wc, i2, fmaf(wb, i1, fmaf(wa, i0, acc[cr][0])));
                    acc[cr][1] = fmaf(wc, i3, fmaf(wb, i2, fmaf(wa, i1, acc[cr][1])));
                    acc[cr][2] = fmaf(wc, i4, fmaf(wb, i3, fmaf(wa, i2, acc[cr][2])));
                    acc[cr][3] = fmaf(wc, i5, fmaf(wb, i4, fmaf(wa, i3, acc[cr][3])));
                }
            }
        }
    }

    if (MODE == 1) {
        // residual 1x1x1 conv over the raw x (64 in-channels), accumulate into acc
        for (int rc0 = 0; rc0 < 64; rc0 += 8) {
            __syncthreads();
            for (int i = tid; i < 8*128; i += 256) {
                int w = i & 127, c = i >> 7;
                sIn[c*128 + w] = xres[((n*CIN_X + rc0 + c)*DD + d)*HW + h*WW + w];
            }
            for (int i = tid; i < 512; i += 256) {
                int c = i & 7, col = i >> 3;
                sW[c*64 + col] = resw[(cob + col)*CIN_X + rc0 + c];
            }
            __syncthreads();
            #pragma unroll
            for (int c = 0; c < 8; c++) {
                const float* rp = &sIn[c*128 + w0];
                float i0 = rp[0], i1 = rp[1], i2 = rp[2], i3 = rp[3];
                #pragma unroll
                for (int cr = 0; cr < 8; cr++) {
                    float wv = sW[c*64 + (cg << 3) + cr];
                    acc[cr][0] = fmaf(wv, i0, acc[cr][0]);
                    acc[cr][1] = fmaf(wv, i1, acc[cr][1]);
                    acc[cr][2] = fmaf(wv, i2, acc[cr][2]);
                    acc[cr][3] = fmaf(wv, i3, acc[cr][3]);
                }
            }
        }
    }

    // epilogue
    #pragma unroll
    for (int cr = 0; cr < 8; cr++) {
        int co = cob + (cg << 3) + cr;
        float4 o;
        float* op = (float*)&o;
        if (MODE == 0) {
            float b  = bias[co];
            float sc = g_s2[n*COUT + co];
            #pragma unroll
            for (int wi = 0; wi < 4; wi++) {
                float v = acc[cr][wi] + b;
                op[wi] = swish_f(v) * sc;
            }
        } else {
            float b = bias[co];    // res_b
            #pragma unroll
            for (int wi = 0; wi < 4; wi++) {
                float v = acc[cr][wi] + b;
                op[wi] = swish_f(v);
            }
        }
        *(float4*)&out[((n*COUT + co)*DD + d)*HW + h*WW + w0] = o;
    }
}

// ---------------------------------------------------------------------------
// Kernel 5: down conv 3x3x3, stride (1,2,2), pad (1,0,0), + down_b
// Block: one (n,od,oh) output row, 64 co. Thread: 4 co x 4 ow.
// ---------------------------------------------------------------------------
__global__ void __launch_bounds__(256, 2) down_kernel(
    const float* __restrict__ wgt,    // (COUT, COUT, 27)
    const float* __restrict__ bias,   // down_b
    float* __restrict__ out)          // (4,128,8,63,63)
{
    constexpr int CI_STEP = 2;
    __shared__ float sIn[CI_STEP*9*132];
    __shared__ float sW[CI_STEP*64*27];

    const int oh  = blockIdx.x;          // 0..62
    const int d   = blockIdx.y & 7;
    const int n   = blockIdx.y >> 3;
    const int cob = blockIdx.z << 6;
    const int tid = threadIdx.x;
    const int wg  = tid & 15;
    const int cg  = tid >> 4;
    const int ow0 = wg << 2;

    float acc[4][4];
    #pragma unroll
    for (int i = 0; i < 4; i++)
        #pragma unroll
        for (int j = 0; j < 4; j++) acc[i][j] = 0.f;

    for (int ci0 = 0; ci0 < COUT; ci0 += CI_STEP) {
        __syncthreads();
        for (int i = tid; i < CI_STEP*9*128; i += 256) {
            int w = i & 127;
            int r = i >> 7;
            int p = r % 9;
            int c = r / 9;
            int kd = p / 3, kh = p - kd*3;
            int id = d + kd - 1;
            int ih = oh*2 + kh;          // always in [0,126]
            float v = 0.f;
            if ((unsigned)id < (unsigned)DD)
                v = g_h2[((n*COUT + ci0 + c)*DD + id)*HW + ih*WW + w];
            sIn[(c*9 + p)*132 + w] = v;
        }
        for (int i = tid; i < CI_STEP*64*27; i += 256) {
            int k   = i % 27;
            int r   = i / 27;
            int col = r & 63;
            int c   = r >> 6;
            sW[(c*64 + col)*27 + k] = wgt[((cob + col)*COUT + ci0 + c)*27 + k];
        }
        __syncthreads();

        #pragma unroll
        for (int c = 0; c < CI_STEP; c++) {
            #pragma unroll
            for (int p = 0; p < 9; p++) {
                const float* rp = &sIn[(c*9 + p)*132 + (ow0 << 1)];
                float i0 = rp[0], i1 = rp[1], i2 = rp[2], i3 = rp[3], i4 = rp[4];
                float i5 = rp[5], i6 = rp[6], i7 = rp[7], i8 = rp[8];
                const float* wp = &sW[(c*64 + (cg << 2))*27 + p*3];
                #pragma unroll
                for (int cr = 0; cr < 4; cr++) {
                    float wa = wp[cr*27 + 0];
                    float wb = wp[cr*27 + 1];
                    float wc = wp[cr*27 + 2];
                    acc[cr][0] = fmaf(wc, i2, fmaf(wb, i1, fmaf(wa, i0, acc[cr][0])));
                    acc[cr][1] = fmaf(wc, i4, fmaf(wb, i3, fmaf(wa, i2, acc[cr][1])));
                    acc[cr][2] = fmaf(wc, i6, fmaf(wb, i5, fmaf(wa, i4, acc[cr][2])));
                    acc[cr][3] = fmaf(wc, i8, fmaf(wb, i7, fmaf(wa, i6, acc[cr][3])));
                }
            }
        }
    }

    #pragma unroll
    for (int cr = 0; cr < 4; cr++) {
        int co = cob + (cg << 2) + cr;
        float b = bias[co];
        #pragma unroll
        for (int wi = 0; wi < 4; wi++) {
            int ow = ow0 + wi;
            if (ow < OW)
                out[((n*COUT + co)*DD + d)*(OH*OW) + oh*OW + ow] = acc[cr][wi] + b;
        }
    }
}

// ---------------------------------------------------------------------------
extern "C" void kernel_launch(void* const* d_in, const int* in_sizes, int n_in,
                              void* d_out, int out_size)
{
    const float* x       = (const float*)d_in[0];
    const float* embed   = (const float*)d_in[1];
    const float* context = (const float*)d_in[2];
    const float* w20     = (const float*)d_in[3];
    const float* b20     = (const float*)d_in[4];
    const float* w21     = (const float*)d_in[5];
    const float* d1_w    = (const float*)d_in[6];
    const float* d1_b    = (const float*)d_in[7];
    const float* d2_w    = (const float*)d_in[8];
    const float* d2_b    = (const float*)d_in[9];
    const float* res_w   = (const float*)d_in[10];
    const float* res_b   = (const float*)d_in[11];
    const float* down_w  = (const float*)d_in[12];
    const float* down_b  = (const float*)d_in[13];
    float* out = (float*)d_out;

    // 1) modulation vectors
    s_kernel<<<1, 512>>>(embed, context, d1_w, d1_b, d2_w, d2_b);

    // 2) act = swish(x + s1)
    act_kernel<<<(BB*CIN_X*DHW/4)/256, 256>>>(x);

    // 3) conv20 + b20 + swish + *s2  -> g_h1
    conv3x3_kernel<64, 0><<<dim3(HH, BB*DD, 2), 256>>>(w20, b20, nullptr, nullptr);

    // 4) conv21 + res(1x1 of x) + res_b + swish -> g_h2
    conv3x3_kernel<128, 1><<<dim3(HH, BB*DD, 2), 256>>>(w21, res_b, x, res_w);

    // 5) strided down conv + down_b -> out
    down_kernel<<<dim3(OH, BB*DD, 2), 256>>>(down_w, down_b, out);
}

// round 3
// speedup vs baseline: 3.8038x; 3.8038x over previous
#include <cuda_runtime.h>
#include <cuda_bf16.h>
#include <cstdint>

// Problem constants
#define BB 4
#define CIN_X 64
#define COUT 128
#define DD 8
#define HH 128
#define WW 128
#define EE 256
#define OH 63
#define OW 63
#define HW (HH*WW)

// ---------------------------------------------------------------------------
// Device-global scratch. Channels-last (NDHWC) bf16 hi/lo split tensors.
// ---------------------------------------------------------------------------
__device__ float g_s1[BB*CIN_X];
__device__ float g_s2[BB*COUT];
__device__ __nv_bfloat16 g_xh[BB*DD*HH*WW*64];   // x, hi part
__device__ __nv_bfloat16 g_xl[BB*DD*HH*WW*64];   // x, lo part
__device__ __nv_bfloat16 g_ah[BB*DD*HH*WW*64];   // swish(x+s1), hi
__device__ __nv_bfloat16 g_al[BB*DD*HH*WW*64];   // swish(x+s1), lo
__device__ __nv_bfloat16 g_h1h[(size_t)BB*DD*HH*WW*128];
__device__ __nv_bfloat16 g_h1l[(size_t)BB*DD*HH*WW*128];
__device__ __nv_bfloat16 g_h2h[(size_t)BB*DD*HH*WW*128];
__device__ __nv_bfloat16 g_h2l[(size_t)BB*DD*HH*WW*128];
// Pre-transposed + pre-swizzled weight tiles: 136 chunks x (128co x 64ci) bf16
// [0,27) conv20 taps; [27,81) conv21 (tap,cihalf); 81 res; [82,136) down
__device__ __nv_bfloat16 g_wh[136*8192];
__device__ __nv_bfloat16 g_wl[136*8192];

__device__ __forceinline__ float swish_f(float v) {
    return v / (1.f + __expf(-v));
}

__device__ __forceinline__ uint32_t smem_u32(const void* p) {
    uint32_t a;
    asm("{ .reg .u64 t; cvta.to.shared.u64 t, %1; cvt.u32.u64 %0, t; }" : "=r"(a) : "l"(p));
    return a;
}

__device__ __forceinline__ uint32_t swz(uint32_t off) {
    return off ^ ((off >> 3) & 0x70);
}

__device__ __forceinline__ void cp_async16(uint32_t dst, const void* src, bool valid) {
    int sz = valid ? 16 : 0;
    asm volatile("cp.async.cg.shared.global [%0], [%1], 16, %2;"
                 :: "r"(dst), "l"(src), "r"(sz));
}

__device__ __forceinline__ void ldm4(uint32_t* r, uint32_t addr) {
    asm volatile("ldmatrix.sync.aligned.m8n8.x4.shared.b16 {%0,%1,%2,%3}, [%4];"
                 : "=r"(r[0]), "=r"(r[1]), "=r"(r[2]), "=r"(r[3]) : "r"(addr));
}

__device__ __forceinline__ void mma16816(float* d, const uint32_t* a, const uint32_t* b) {
    asm volatile(
        "mma.sync.aligned.m16n8k16.row.col.f32.bf16.bf16.f32 "
        "{%0,%1,%2,%3}, {%4,%5,%6,%7}, {%8,%9}, {%0,%1,%2,%3};"
        : "+f"(d[0]), "+f"(d[1]), "+f"(d[2]), "+f"(d[3])
        : "r"(a[0]), "r"(a[1]), "r"(a[2]), "r"(a[3]), "r"(b[0]), "r"(b[1]));
}

// ---------------------------------------------------------------------------
// Kernel 1: s1 = embed @ d1_w + d1_b; s2 = context @ d2_w + d2_b
// ---------------------------------------------------------------------------
__global__ void s_kernel(const float* __restrict__ embed,
                         const float* __restrict__ context,
                         const float* __restrict__ d1w, const float* __restrict__ d1b,
                         const float* __restrict__ d2w, const float* __restrict__ d2b)
{
    int t = threadIdx.x;   // 512 threads
    if (t < BB*CIN_X) {
        int n = t >> 6, c = t & 63;
        float acc = d1b[c];
        #pragma unroll 4
        for (int e = 0; e < EE; e++) acc += embed[n*EE + e] * d1w[e*CIN_X + c];
        g_s1[t] = acc;
    }
    {
        int n = t >> 7, c = t & 127;
        float acc = d2b[c];
        #pragma unroll 4
        for (int e = 0; e < EE; e++) acc += context[n*EE + e] * d2w[e*COUT + c];
        g_s2[t] = acc;
    }
}

// ---------------------------------------------------------------------------
// Kernel 2: NCDHW fp32 x -> channels-last bf16 hi/lo for x and act=swish(x+s1)
// ---------------------------------------------------------------------------
__global__ void __launch_bounds__(256) cvt_x_kernel(const float* __restrict__ x)
{
    __shared__ float sm[64*133];
    const int h  = blockIdx.x;
    const int nd = blockIdx.y;
    const int n  = nd >> 3, d = nd & 7;
    const int tid = threadIdx.x;

    for (int i = tid; i < 64*128; i += 256) {
        int ci = i >> 7, w = i & 127;
        sm[ci*133 + w] = x[((size_t)(n*64 + ci)*8 + d)*HW + h*128 + w];
    }
    __syncthreads();
    size_t base = ((size_t)nd*128 + h) * 128 * 64;
    for (int i = tid; i < 64*128; i += 256) {
        int w = i >> 6, ci = i & 63;
        float v = sm[ci*133 + w];
        float a = swish_f(v + g_s1[n*64 + ci]);
        __nv_bfloat16 xh = __float2bfloat16(v);
        __nv_bfloat16 xl = __float2bfloat16(v - __bfloat162float(xh));
        __nv_bfloat16 ah = __float2bfloat16(a);
        __nv_bfloat16 al = __float2bfloat16(a - __bfloat162float(ah));
        size_t o = base + (size_t)w*64 + ci;
        g_xh[o] = xh; g_xl[o] = xl; g_ah[o] = ah; g_al[o] = al;
    }
}

// ---------------------------------------------------------------------------
// Kernel 3: weight tiles, transposed (co-row, ci-col), bf16 hi/lo, SW128-swizzled
// ---------------------------------------------------------------------------
__global__ void wcvt_kernel(const float* __restrict__ w20,
                            const float* __restrict__ w21,
                            const float* __restrict__ resw,
                            const float* __restrict__ dwn)
{
    int c = blockIdx.x;     // 0..135
    int tid = threadIdx.x;
    for (int i = tid; i < 8192; i += 256) {
        int co = i >> 6, ci = i & 63;
        float v;
        if (c < 27) {
            v = w20[(co*64 + ci)*27 + c];
        } else if (c < 81) {
            int cc = c - 27; int tap = cc >> 1, half = cc & 1;
            v = w21[(co*128 + half*64 + ci)*27 + tap];
        } else if (c == 81) {
            v = resw[co*64 + ci];
        } else {
            int cc = c - 82; int tap = cc >> 1, half = cc & 1;
            v = dwn[(co*128 + half*64 + ci)*27 + tap];
        }
        __nv_bfloat16 hb = __float2bfloat16(v);
        __nv_bfloat16 lb = __float2bfloat16(v - __bfloat162float(hb));
        uint32_t sw = swz(co*128 + ci*2);
        *(__nv_bfloat16*)((char*)g_wh + (size_t)c*16384 + sw) = hb;
        *(__nv_bfloat16*)((char*)g_wl + (size_t)c*16384 + sw) = lb;
    }
}

// ---------------------------------------------------------------------------
// Implicit-GEMM conv via mma.sync bf16x3 split. One CTA per (n,d,h|oh) row.
// M=128 px, N=128 co. K chunks of 64.
// MODE 0: conv20  (act_cl, 64ci, 27 chunks)    epi: +b20, swish, *s2 -> h1_cl
// MODE 1: conv21  (h1_cl, 128ci, 54 chunks) + res tap (x_cl) epi: +res_b, swish -> h2_cl
// MODE 2: down    (h2_cl, 128ci, 54 chunks, stride-2 W/H)    epi: +down_b -> out
// ---------------------------------------------------------------------------
#define STAGE_BYTES 65536   // aH 16K | aL 16K | bH 16K | bL 16K
#define GEMM_SMEM   (2*STAGE_BYTES)

template<int MODE>
__global__ void __launch_bounds__(256, 1) conv_mma(const float* __restrict__ bias,
                                                   float* __restrict__ outp)
{
    extern __shared__ __align__(1024) char smem[];
    constexpr int NCHUNK = (MODE == 0) ? 27 : (MODE == 1) ? 55 : 54;
    constexpr int WBASE  = (MODE == 0) ? 0  : (MODE == 1) ? 27 : 82;

    const uint32_t sb = smem_u32(smem);
    const int tid  = threadIdx.x;
    const int wid  = tid >> 5;
    const int lane = tid & 31;
    const int nd = blockIdx.y, n = nd >> 3, d = nd & 7;
    const int hq = blockIdx.x;

    auto stage = [&](int c, int buf) {
        int ciStride = 64, kw = 1;
        bool pv = true;
        const char *srcH = nullptr, *srcL = nullptr;
        if (MODE == 1 && c == 54) {
            size_t pb = ((size_t)(nd*128 + hq)) * 128;
            srcH = (const char*)(g_xh + pb*64);
            srcL = (const char*)(g_xl + pb*64);
        } else {
            int tap, half;
            if (MODE == 0) { tap = c; half = 0; ciStride = 64; }
            else           { tap = c >> 1; half = c & 1; ciStride = 128; }
            int kd = tap / 9, kh = (tap / 3) % 3;
            kw = tap % 3;
            int id = d + kd - 1;
            int ih = (MODE == 2) ? (hq*2 + kh) : (hq + kh - 1);
            pv = ((unsigned)id < 8u) && ((unsigned)ih < 128u);
            if (pv) {
                size_t pb = ((size_t)((n*8 + id)*128 + ih)) * 128;
                if (MODE == 0)      { srcH = (const char*)(g_ah  + pb*64);
                                      srcL = (const char*)(g_al  + pb*64); }
                else if (MODE == 1) { srcH = (const char*)(g_h1h + pb*128 + half*64);
                                      srcL = (const char*)(g_h1l + pb*128 + half*64); }
                else                { srcH = (const char*)(g_h2h + pb*128 + half*64);
                                      srcL = (const char*)(g_h2l + pb*128 + half*64); }
            }
        }
        uint32_t aH = sb + buf*STAGE_BYTES;
        uint32_t aL = aH + 16384, bHs = aH + 32768, bLs = aH + 49152;
        const char* dummy = (const char*)g_wh;
        #pragma unroll
        for (int t = 0; t < 4; t++) {
            int i = tid + t*256;
            int p = i >> 3, q = i & 7;
            int iw = (MODE == 2) ? (2*p + kw) : (p + kw - 1);
            bool v = pv && ((unsigned)iw < 128u) && (MODE != 2 || p < 63);
            size_t off = (size_t)iw * ciStride * 2 + q*16;
            uint32_t so = swz(p*128 + q*16);
            cp_async16(aH + so, v ? srcH + off : dummy, v);
            cp_async16(aL + so, v ? srcL + off : dummy, v);
        }
        const char* wH = (const char*)g_wh + (size_t)(WBASE + c)*16384;
        const char* wL = (const char*)g_wl + (size_t)(WBASE + c)*16384;
        #pragma unroll
        for (int t = 0; t < 4; t++) {
            int i = (tid + t*256)*16;
            cp_async16(bHs + i, wH + i, true);
            cp_async16(bLs + i, wL + i, true);
        }
    };

    // prologue: two chunks in flight
    stage(0, 0);
    asm volatile("cp.async.commit_group;");
    stage(1, 1);
    asm volatile("cp.async.commit_group;");

    const int m0 = (wid & 3) * 32;
    const int n0 = (wid >> 2) * 64;
    float acc[2][8][4];
    #pragma unroll
    for (int a = 0; a < 2; a++)
        #pragma unroll
        for (int b = 0; b < 8; b++)
            #pragma unroll
            for (int q = 0; q < 4; q++) acc[a][b][q] = 0.f;

    for (int c = 0; c < NCHUNK; c++) {
        int buf = c & 1;
        asm volatile("cp.async.wait_group 1;" ::: "memory");
        __syncthreads();
        uint32_t aH = sb + buf*STAGE_BYTES;
        uint32_t aL = aH + 16384, bH = aH + 32768, bL = aH + 49152;
        const int sub = lane >> 3, r = lane & 7;

        #pragma unroll
        for (int kk = 0; kk < 4; kk++) {
            const int k0b = kk*32;
            uint32_t ahF[2][4], alF[2][4], bhF[4][4], blF[4][4];
            #pragma unroll
            for (int fm = 0; fm < 2; fm++) {
                uint32_t so = swz((m0 + fm*16 + (sub & 1)*8 + r)*128 + k0b + (sub >> 1)*16);
                ldm4(ahF[fm], aH + so);
                ldm4(alF[fm], aL + so);
            }
            #pragma unroll
            for (int nb = 0; nb < 4; nb++) {
                uint32_t so = swz((n0 + nb*16 + (sub >> 1)*8 + r)*128 + k0b + (sub & 1)*16);
                ldm4(bhF[nb], bH + so);
                ldm4(blF[nb], bL + so);
            }
            #pragma unroll
            for (int fm = 0; fm < 2; fm++) {
                #pragma unroll
                for (int j = 0; j < 8; j++) {
                    const uint32_t* bh = &bhF[j >> 1][(j & 1)*2];
                    const uint32_t* bl = &blF[j >> 1][(j & 1)*2];
                    mma16816(acc[fm][j], ahF[fm], bh);
                    mma16816(acc[fm][j], ahF[fm], bl);
                    mma16816(acc[fm][j], alF[fm], bh);
                }
            }
        }
        __syncthreads();
        if (c + 2 < NCHUNK) stage(c + 2, buf);
        asm volatile("cp.async.commit_group;");
    }
    asm volatile("cp.async.wait_all;" ::: "memory");

    // ---- epilogue ----
    const size_t rowBase = (size_t)(nd*128 + hq) * 128;
    #pragma unroll
    for (int fm = 0; fm < 2; fm++) {
        #pragma unroll
        for (int j = 0; j < 8; j++) {
            int c0 = n0 + j*8 + (lane & 3)*2;
            int r0 = m0 + fm*16 + (lane >> 2);
            float b0v = bias[c0], b1v = bias[c0 + 1];
            #pragma unroll
            for (int rr = 0; rr < 2; rr++) {
                int row = r0 + rr*8;
                float v0 = acc[fm][j][rr*2 + 0] + b0v;
                float v1 = acc[fm][j][rr*2 + 1] + b1v;
                if (MODE == 2) {
                    if (row < OW) {
                        size_t ob = ((size_t)(n*128 + c0)*8 + d)*(OH*OW) + hq*OW + row;
                        outp[ob] = v0;
                        outp[ob + (size_t)8*(OH*OW)] = v1;
                    }
                } else {
                    if (MODE == 0) {
                        v0 = swish_f(v0) * g_s2[n*128 + c0];
                        v1 = swish_f(v1) * g_s2[n*128 + c0 + 1];
                    } else {
                        v0 = swish_f(v0);
                        v1 = swish_f(v1);
                    }
                    __nv_bfloat16 h0 = __float2bfloat16(v0);
                    __nv_bfloat16 h1 = __float2bfloat16(v1);
                    __nv_bfloat16 l0 = __float2bfloat16(v0 - __bfloat162float(h0));
                    __nv_bfloat16 l1 = __float2bfloat16(v1 - __bfloat162float(h1));
                    uint32_t hp = (uint32_t)__bfloat16_as_ushort(h1) << 16 |
                                  __bfloat16_as_ushort(h0);
                    uint32_t lp = (uint32_t)__bfloat16_as_ushort(l1) << 16 |
                                  __bfloat16_as_ushort(l0);
                    size_t ob = (rowBase + row)*128 + c0;
                    if (MODE == 0) {
                        *(uint32_t*)(g_h1h + ob) = hp;
                        *(uint32_t*)(g_h1l + ob) = lp;
                    } else {
                        *(uint32_t*)(g_h2h + ob) = hp;
                        *(uint32_t*)(g_h2l + ob) = lp;
                    }
                }
            }
        }
    }
}

// ---------------------------------------------------------------------------
extern "C" void kernel_launch(void* const* d_in, const int* in_sizes, int n_in,
                              void* d_out, int out_size)
{
    const float* x       = (const float*)d_in[0];
    const float* embed   = (const float*)d_in[1];
    const float* context = (const float*)d_in[2];
    const float* w20     = (const float*)d_in[3];
    const float* b20     = (const float*)d_in[4];
    const float* w21     = (const float*)d_in[5];
    const float* d1_w    = (const float*)d_in[6];
    const float* d1_b    = (const float*)d_in[7];
    const float* d2_w    = (const float*)d_in[8];
    const float* d2_b    = (const float*)d_in[9];
    const float* res_w   = (const float*)d_in[10];
    const float* res_b   = (const float*)d_in[11];
    const float* down_w  = (const float*)d_in[12];
    const float* down_b  = (const float*)d_in[13];
    float* out = (float*)d_out;

    cudaFuncSetAttribute(conv_mma<0>, cudaFuncAttributeMaxDynamicSharedMemorySize, GEMM_SMEM);
    cudaFuncSetAttribute(conv_mma<1>, cudaFuncAttributeMaxDynamicSharedMemorySize, GEMM_SMEM);
    cudaFuncSetAttribute(conv_mma<2>, cudaFuncAttributeMaxDynamicSharedMemorySize, GEMM_SMEM);

    s_kernel<<<1, 512>>>(embed, context, d1_w, d1_b, d2_w, d2_b);
    cvt_x_kernel<<<dim3(HH, BB*DD), 256>>>(x);
    wcvt_kernel<<<136, 256>>>(w20, w21, res_w, down_w);

    conv_mma<0><<<dim3(HH, BB*DD), 256, GEMM_SMEM>>>(b20,    nullptr);
    conv_mma<1><<<dim3(HH, BB*DD), 256, GEMM_SMEM>>>(res_b,  nullptr);
    conv_mma<2><<<dim3(OH, BB*DD), 256, GEMM_SMEM>>>(down_b, out);
}

// round 4
// speedup vs baseline: 4.3537x; 1.1446x over previous
#include <cuda_runtime.h>
#include <cuda_bf16.h>
#include <cstdint>

// Problem constants
#define BB 4
#define CIN_X 64
#define COUT 128
#define DD 8
#define HH 128
#define WW 128
#define EE 256
#define OH 63
#define OW 63
#define HW (HH*WW)

// ---------------------------------------------------------------------------
// Device-global scratch. Channels-last (NDHWC) bf16 hi/lo split tensors.
// ---------------------------------------------------------------------------
__device__ float g_s1[BB*CIN_X];
__device__ float g_s2[BB*COUT];
__device__ __nv_bfloat16 g_xh[BB*DD*HH*WW*64];
__device__ __nv_bfloat16 g_xl[BB*DD*HH*WW*64];
__device__ __nv_bfloat16 g_ah[BB*DD*HH*WW*64];
__device__ __nv_bfloat16 g_al[BB*DD*HH*WW*64];
__device__ __nv_bfloat16 g_h1h[(size_t)BB*DD*HH*WW*128];
__device__ __nv_bfloat16 g_h1l[(size_t)BB*DD*HH*WW*128];
__device__ __nv_bfloat16 g_h2h[(size_t)BB*DD*HH*WW*128];
__device__ __nv_bfloat16 g_h2l[(size_t)BB*DD*HH*WW*128];
// Pre-transposed + pre-swizzled weight tiles: 136 chunks x (128co x 64ci) bf16
// [0,27) conv20 taps; [27,81) conv21 (tap,cihalf); 81 res; [82,136) down
__device__ __nv_bfloat16 g_wh[136*8192];
__device__ __nv_bfloat16 g_wl[136*8192];

__device__ __forceinline__ float swish_f(float v) {
    return v / (1.f + __expf(-v));
}

__device__ __forceinline__ uint32_t smem_u32(const void* p) {
    uint32_t a;
    asm("{ .reg .u64 t; cvta.to.shared.u64 t, %1; cvt.u32.u64 %0, t; }" : "=r"(a) : "l"(p));
    return a;
}

__device__ __forceinline__ uint32_t swz(uint32_t off) {
    return off ^ ((off >> 3) & 0x70);
}

__device__ __forceinline__ void cp_async16(uint32_t dst, const void* src, bool valid) {
    int sz = valid ? 16 : 0;
    asm volatile("cp.async.cg.shared.global [%0], [%1], 16, %2;"
                 :: "r"(dst), "l"(src), "r"(sz));
}

__device__ __forceinline__ void ldm4(uint32_t* r, uint32_t addr) {
    asm volatile("ldmatrix.sync.aligned.m8n8.x4.shared.b16 {%0,%1,%2,%3}, [%4];"
                 : "=r"(r[0]), "=r"(r[1]), "=r"(r[2]), "=r"(r[3]) : "r"(addr));
}

__device__ __forceinline__ void mma16816(float* d, const uint32_t* a, const uint32_t* b) {
    asm volatile(
        "mma.sync.aligned.m16n8k16.row.col.f32.bf16.bf16.f32 "
        "{%0,%1,%2,%3}, {%4,%5,%6,%7}, {%8,%9}, {%0,%1,%2,%3};"
        : "+f"(d[0]), "+f"(d[1]), "+f"(d[2]), "+f"(d[3])
        : "r"(a[0]), "r"(a[1]), "r"(a[2]), "r"(a[3]), "r"(b[0]), "r"(b[1]));
}

// ---------------------------------------------------------------------------
// Kernel 1: s1 = embed @ d1_w + d1_b; s2 = context @ d2_w + d2_b
// ---------------------------------------------------------------------------
__global__ void s_kernel(const float* __restrict__ embed,
                         const float* __restrict__ context,
                         const float* __restrict__ d1w, const float* __restrict__ d1b,
                         const float* __restrict__ d2w, const float* __restrict__ d2b)
{
    int t = threadIdx.x;   // 512 threads
    if (t < BB*CIN_X) {
        int n = t >> 6, c = t & 63;
        float acc = d1b[c];
        #pragma unroll 4
        for (int e = 0; e < EE; e++) acc += embed[n*EE + e] * d1w[e*CIN_X + c];
        g_s1[t] = acc;
    }
    {
        int n = t >> 7, c = t & 127;
        float acc = d2b[c];
        #pragma unroll 4
        for (int e = 0; e < EE; e++) acc += context[n*EE + e] * d2w[e*COUT + c];
        g_s2[t] = acc;
    }
}

// ---------------------------------------------------------------------------
// Kernel 2: NCDHW fp32 x -> channels-last bf16 hi/lo for x and act=swish(x+s1)
// ---------------------------------------------------------------------------
__global__ void __launch_bounds__(256) cvt_x_kernel(const float* __restrict__ x)
{
    __shared__ float sm[64*133];
    const int h  = blockIdx.x;
    const int nd = blockIdx.y;
    const int n  = nd >> 3, d = nd & 7;
    const int tid = threadIdx.x;

    for (int i = tid; i < 64*128; i += 256) {
        int ci = i >> 7, w = i & 127;
        sm[ci*133 + w] = x[((size_t)(n*64 + ci)*8 + d)*HW + h*128 + w];
    }
    __syncthreads();
    size_t base = ((size_t)nd*128 + h) * 128 * 64;
    for (int i = tid; i < 64*128; i += 256) {
        int w = i >> 6, ci = i & 63;
        float v = sm[ci*133 + w];
        float a = swish_f(v + g_s1[n*64 + ci]);
        __nv_bfloat16 xh = __float2bfloat16(v);
        __nv_bfloat16 xl = __float2bfloat16(v - __bfloat162float(xh));
        __nv_bfloat16 ah = __float2bfloat16(a);
        __nv_bfloat16 al = __float2bfloat16(a - __bfloat162float(ah));
        size_t o = base + (size_t)w*64 + ci;
        g_xh[o] = xh; g_xl[o] = xl; g_ah[o] = ah; g_al[o] = al;
    }
}

// ---------------------------------------------------------------------------
// Kernel 3: weight tiles, transposed (co-row, ci-col), bf16 hi/lo, SW128-swizzled
// ---------------------------------------------------------------------------
__global__ void wcvt_kernel(const float* __restrict__ w20,
                            const float* __restrict__ w21,
                            const float* __restrict__ resw,
                            const float* __restrict__ dwn)
{
    int c = blockIdx.x;     // 0..135
    int tid = threadIdx.x;
    for (int i = tid; i < 8192; i += 256) {
        int co = i >> 6, ci = i & 63;
        float v;
        if (c < 27) {
            v = w20[(co*64 + ci)*27 + c];
        } else if (c < 81) {
            int cc = c - 27; int tap = cc >> 1, half = cc & 1;
            v = w21[(co*128 + half*64 + ci)*27 + tap];
        } else if (c == 81) {
            v = resw[co*64 + ci];
        } else {
            int cc = c - 82; int tap = cc >> 1, half = cc & 1;
            v = dwn[(co*128 + half*64 + ci)*27 + tap];
        }
        __nv_bfloat16 hb = __float2bfloat16(v);
        __nv_bfloat16 lb = __float2bfloat16(v - __bfloat162float(hb));
        uint32_t sw = swz(co*128 + ci*2);
        *(__nv_bfloat16*)((char*)g_wh + (size_t)c*16384 + sw) = hb;
        *(__nv_bfloat16*)((char*)g_wl + (size_t)c*16384 + sw) = lb;
    }
}

// ---------------------------------------------------------------------------
// Implicit-GEMM conv via mma.sync bf16x3 split. M=128 px, N=128 co, K chunks of 64.
// MODE 0: conv20  one (n,d,h) row         epi: +b20, swish, *s2 -> h1_cl
// MODE 1: conv21  one (n,d,h) row + res   epi: +res_b, swish -> h2_cl
// MODE 2: down    TWO oh rows packed (M = 2x64), stride-2 W/H  epi: +down_b -> out
// 3-stage cp.async pipeline (192 KB smem).
// ---------------------------------------------------------------------------
#define STAGE_BYTES 65536   // aH 16K | aL 16K | bH 16K | bL 16K
#define NSTAGE 3
#define GEMM_SMEM   (NSTAGE*STAGE_BYTES)

template<int MODE>
__global__ void __launch_bounds__(256, 1) conv_mma(const float* __restrict__ bias,
                                                   float* __restrict__ outp)
{
    extern __shared__ __align__(1024) char smem[];
    constexpr int NCHUNK = (MODE == 0) ? 27 : (MODE == 1) ? 55 : 54;
    constexpr int WBASE  = (MODE == 0) ? 0  : (MODE == 1) ? 27 : 82;

    const uint32_t sb = smem_u32(smem);
    const int tid  = threadIdx.x;
    const int wid  = tid >> 5;
    const int lane = tid & 31;
    const int nd = blockIdx.y, n = nd >> 3, d = nd & 7;
    const int hq = blockIdx.x;   // h (MODE 0/1); oh-pair index (MODE 2)

    auto stage = [&](int c, int buf) {
        uint32_t aH = sb + buf*STAGE_BYTES;
        uint32_t aL = aH + 16384, bHs = aH + 32768, bLs = aH + 49152;
        const char* dummy = (const char*)g_wh;

        if (MODE == 2) {
            int tap = c >> 1, half = c & 1;
            int kd = tap / 9, kh = (tap / 3) % 3, kw = tap % 3;
            int id = d + kd - 1;
            bool pvd = ((unsigned)id < 8u);
            const char* plH = (const char*)(g_h2h + ((size_t)(n*8 + id)*HW)*128 + half*64);
            const char* plL = (const char*)(g_h2l + ((size_t)(n*8 + id)*HW)*128 + half*64);
            #pragma unroll
            for (int t = 0; t < 4; t++) {
                int i = tid + t*256;
                int p = i >> 3, q = i & 7;
                int ohl = p >> 6, ow = p & 63;
                int oh = hq*2 + ohl;
                int iw = 2*ow + kw;
                int ih = oh*2 + kh;
                bool v = pvd && (ow < 63) && (oh < 63);
                size_t off = ((size_t)ih*128 + iw)*256 + q*16;
                uint32_t so = swz(p*128 + q*16);
                cp_async16(aH + so, v ? plH + off : dummy, v);
                cp_async16(aL + so, v ? plL + off : dummy, v);
            }
        } else {
            int ciStride = 64, kw = 1;
            bool pv = true;
            const char *srcH = nullptr, *srcL = nullptr;
            if (MODE == 1 && c == 54) {
                size_t pb = ((size_t)(nd*128 + hq)) * 128;
                srcH = (const char*)(g_xh + pb*64);
                srcL = (const char*)(g_xl + pb*64);
            } else {
                int tap, half;
                if (MODE == 0) { tap = c; half = 0; ciStride = 64; }
                else           { tap = c >> 1; half = c & 1; ciStride = 128; }
                int kd = tap / 9, kh = (tap / 3) % 3;
                kw = tap % 3;
                int id = d + kd - 1;
                int ih = hq + kh - 1;
                pv = ((unsigned)id < 8u) && ((unsigned)ih < 128u);
                if (pv) {
                    size_t pb = ((size_t)((n*8 + id)*128 + ih)) * 128;
                    if (MODE == 0) { srcH = (const char*)(g_ah  + pb*64);
                                     srcL = (const char*)(g_al  + pb*64); }
                    else           { srcH = (const char*)(g_h1h + pb*128 + half*64);
                                     srcL = (const char*)(g_h1l + pb*128 + half*64); }
                }
            }
            #pragma unroll
            for (int t = 0; t < 4; t++) {
                int i = tid + t*256;
                int p = i >> 3, q = i & 7;
                int iw = p + kw - 1;
                bool v = pv && ((unsigned)iw < 128u);
                size_t off = (size_t)iw * ciStride * 2 + q*16;
                uint32_t so = swz(p*128 + q*16);
                cp_async16(aH + so, v ? srcH + off : dummy, v);
                cp_async16(aL + so, v ? srcL + off : dummy, v);
            }
        }
        const char* wH = (const char*)g_wh + (size_t)(WBASE + c)*16384;
        const char* wL = (const char*)g_wl + (size_t)(WBASE + c)*16384;
        #pragma unroll
        for (int t = 0; t < 4; t++) {
            int i = (tid + t*256)*16;
            cp_async16(bHs + i, wH + i, true);
            cp_async16(bLs + i, wL + i, true);
        }
    };

    // prologue: two chunks in flight
    stage(0, 0);
    asm volatile("cp.async.commit_group;");
    stage(1, 1);
    asm volatile("cp.async.commit_group;");

    const int m0 = (wid & 3) * 32;
    const int n0 = (wid >> 2) * 64;
    float acc[2][8][4];
    #pragma unroll
    for (int a = 0; a < 2; a++)
        #pragma unroll
        for (int b = 0; b < 8; b++)
            #pragma unroll
            for (int q = 0; q < 4; q++) acc[a][b][q] = 0.f;

    int bufc = 0;  // c % 3
    for (int c = 0; c < NCHUNK; c++) {
        asm volatile("cp.async.wait_group 1;" ::: "memory");
        __syncthreads();
        // stage chunk c+2 into buffer (c+2)%3 (freed after compute of c-1)
        int bufn = bufc + 2; if (bufn >= 3) bufn -= 3;
        if (c + 2 < NCHUNK) stage(c + 2, bufn);
        asm volatile("cp.async.commit_group;");

        uint32_t aH = sb + bufc*STAGE_BYTES;
        uint32_t aL = aH + 16384, bH = aH + 32768, bL = aH + 49152;
        const int sub = lane >> 3, r = lane & 7;

        #pragma unroll
        for (int kk = 0; kk < 4; kk++) {
            const int k0b = kk*32;
            uint32_t ahF[2][4], alF[2][4], bhF[4][4], blF[4][4];
            #pragma unroll
            for (int fm = 0; fm < 2; fm++) {
                uint32_t so = swz((m0 + fm*16 + (sub & 1)*8 + r)*128 + k0b + (sub >> 1)*16);
                ldm4(ahF[fm], aH + so);
                ldm4(alF[fm], aL + so);
            }
            #pragma unroll
            for (int nb = 0; nb < 4; nb++) {
                uint32_t so = swz((n0 + nb*16 + (sub >> 1)*8 + r)*128 + k0b + (sub & 1)*16);
                ldm4(bhF[nb], bH + so);
                ldm4(blF[nb], bL + so);
            }
            #pragma unroll
            for (int fm = 0; fm < 2; fm++) {
                #pragma unroll
                for (int j = 0; j < 8; j++) {
                    const uint32_t* bh = &bhF[j >> 1][(j & 1)*2];
                    const uint32_t* bl = &blF[j >> 1][(j & 1)*2];
                    mma16816(acc[fm][j], ahF[fm], bh);
                    mma16816(acc[fm][j], ahF[fm], bl);
                    mma16816(acc[fm][j], alF[fm], bh);
                }
            }
        }
        bufc++; if (bufc >= 3) bufc = 0;
    }
    asm volatile("cp.async.wait_all;" ::: "memory");

    // ---- epilogue ----
    const size_t rowBase = (size_t)(nd*128 + hq) * 128;
    #pragma unroll
    for (int fm = 0; fm < 2; fm++) {
        #pragma unroll
        for (int j = 0; j < 8; j++) {
            int c0 = n0 + j*8 + (lane & 3)*2;
            int r0 = m0 + fm*16 + (lane >> 2);
            float b0v = bias[c0], b1v = bias[c0 + 1];
            #pragma unroll
            for (int rr = 0; rr < 2; rr++) {
                int row = r0 + rr*8;
                float v0 = acc[fm][j][rr*2 + 0] + b0v;
                float v1 = acc[fm][j][rr*2 + 1] + b1v;
                if (MODE == 2) {
                    int ohl = row >> 6, ow = row & 63;
                    int oh = hq*2 + ohl;
                    if (ow < OW && oh < OH) {
                        size_t ob = ((size_t)(n*128 + c0)*8 + d)*(OH*OW) + oh*OW + ow;
                        outp[ob] = v0;
                        outp[ob + (size_t)8*(OH*OW)] = v1;
                    }
                } else {
                    if (MODE == 0) {
                        v0 = swish_f(v0) * g_s2[n*128 + c0];
                        v1 = swish_f(v1) * g_s2[n*128 + c0 + 1];
                    } else {
                        v0 = swish_f(v0);
                        v1 = swish_f(v1);
                    }
                    __nv_bfloat16 h0 = __float2bfloat16(v0);
                    __nv_bfloat16 h1 = __float2bfloat16(v1);
                    __nv_bfloat16 l0 = __float2bfloat16(v0 - __bfloat162float(h0));
                    __nv_bfloat16 l1 = __float2bfloat16(v1 - __bfloat162float(h1));
                    uint32_t hp = (uint32_t)__bfloat16_as_ushort(h1) << 16 |
                                  __bfloat16_as_ushort(h0);
                    uint32_t lp = (uint32_t)__bfloat16_as_ushort(l1) << 16 |
                                  __bfloat16_as_ushort(l0);
                    size_t ob = (rowBase + row)*128 + c0;
                    if (MODE == 0) {
                        *(uint32_t*)(g_h1h + ob) = hp;
                        *(uint32_t*)(g_h1l + ob) = lp;
                    } else {
                        *(uint32_t*)(g_h2h + ob) = hp;
                        *(uint32_t*)(g_h2l + ob) = lp;
                    }
                }
            }
        }
    }
}

// ---------------------------------------------------------------------------
extern "C" void kernel_launch(void* const* d_in, const int* in_sizes, int n_in,
                              void* d_out, int out_size)
{
    const float* x       = (const float*)d_in[0];
    const float* embed   = (const float*)d_in[1];
    const float* context = (const float*)d_in[2];
    const float* w20     = (const float*)d_in[3];
    const float* b20     = (const float*)d_in[4];
    const float* w21     = (const float*)d_in[5];
    const float* d1_w    = (const float*)d_in[6];
    const float* d1_b    = (const float*)d_in[7];
    const float* d2_w    = (const float*)d_in[8];
    const float* d2_b    = (const float*)d_in[9];
    const float* res_w   = (const float*)d_in[10];
    const float* res_b   = (const float*)d_in[11];
    const float* down_w  = (const float*)d_in[12];
    const float* down_b  = (const float*)d_in[13];
    float* out = (float*)d_out;

    cudaFuncSetAttribute(conv_mma<0>, cudaFuncAttributeMaxDynamicSharedMemorySize, GEMM_SMEM);
    cudaFuncSetAttribute(conv_mma<1>, cudaFuncAttributeMaxDynamicSharedMemorySize, GEMM_SMEM);
    cudaFuncSetAttribute(conv_mma<2>, cudaFuncAttributeMaxDynamicSharedMemorySize, GEMM_SMEM);

    s_kernel<<<1, 512>>>(embed, context, d1_w, d1_b, d2_w, d2_b);
    cvt_x_kernel<<<dim3(HH, BB*DD), 256>>>(x);
    wcvt_kernel<<<136, 256>>>(w20, w21, res_w, down_w);

    conv_mma<0><<<dim3(HH, BB*DD), 256, GEMM_SMEM>>>(b20,    nullptr);
    conv_mma<1><<<dim3(HH, BB*DD), 256, GEMM_SMEM>>>(res_b,  nullptr);
    conv_mma<2><<<dim3(32, BB*DD), 256, GEMM_SMEM>>>(down_b, out);
}

// round 5
// speedup vs baseline: 9.1092x; 2.0923x over previous
#include <cuda_runtime.h>
#include <cuda_fp16.h>
#include <cstdint>

// Problem constants
#define BB 4
#define CIN_X 64
#define COUT 128
#define DD 8
#define HH 128
#define WW 128
#define EE 256
#define OH 63
#define OW 63
#define HW (HH*WW)

// ---------------------------------------------------------------------------
// Device-global scratch. Channels-last (NDHWC) fp16 tensors.
// ---------------------------------------------------------------------------
__device__ float g_s1[BB*CIN_X];
__device__ float g_s2[BB*COUT];
__device__ __half g_x[BB*DD*HH*WW*64];            // x (for residual tap)
__device__ __half g_a[BB*DD*HH*WW*64];            // swish(x+s1)
__device__ __half g_h1[(size_t)BB*DD*HH*WW*128];  // after conv20 epi
__device__ __half g_h2[(size_t)BB*DD*HH*WW*128];  // after conv21 epi
// Pre-transposed + pre-swizzled weight tiles: 136 chunks x (128co x 64ci) fp16
// [0,27) conv20 taps; [27,81) conv21 (tap,cihalf); 81 res; [82,136) down
__device__ __half g_w[136*8192];

__device__ __forceinline__ float swish_f(float v) {
    return v / (1.f + __expf(-v));
}

__device__ __forceinline__ uint32_t smem_u32(const void* p) {
    uint32_t a;
    asm("{ .reg .u64 t; cvta.to.shared.u64 t, %1; cvt.u32.u64 %0, t; }" : "=r"(a) : "l"(p));
    return a;
}

__device__ __forceinline__ uint32_t swz(uint32_t off) {
    return off ^ ((off >> 3) & 0x70);
}

__device__ __forceinline__ void cp_async16(uint32_t dst, const void* src, bool valid) {
    int sz = valid ? 16 : 0;
    asm volatile("cp.async.cg.shared.global [%0], [%1], 16, %2;"
                 :: "r"(dst), "l"(src), "r"(sz));
}

__device__ __forceinline__ void ldm4(uint32_t* r, uint32_t addr) {
    asm volatile("ldmatrix.sync.aligned.m8n8.x4.shared.b16 {%0,%1,%2,%3}, [%4];"
                 : "=r"(r[0]), "=r"(r[1]), "=r"(r[2]), "=r"(r[3]) : "r"(addr));
}

__device__ __forceinline__ void mma16816(float* d, const uint32_t* a, const uint32_t* b) {
    asm volatile(
        "mma.sync.aligned.m16n8k16.row.col.f32.f16.f16.f32 "
        "{%0,%1,%2,%3}, {%4,%5,%6,%7}, {%8,%9}, {%0,%1,%2,%3};"
        : "+f"(d[0]), "+f"(d[1]), "+f"(d[2]), "+f"(d[3])
        : "r"(a[0]), "r"(a[1]), "r"(a[2]), "r"(a[3]), "r"(b[0]), "r"(b[1]));
}

// ---------------------------------------------------------------------------
// Kernel 1: s1 = embed @ d1_w + d1_b; s2 = context @ d2_w + d2_b
// ---------------------------------------------------------------------------
__global__ void s_kernel(const float* __restrict__ embed,
                         const float* __restrict__ context,
                         const float* __restrict__ d1w, const float* __restrict__ d1b,
                         const float* __restrict__ d2w, const float* __restrict__ d2b)
{
    int t = threadIdx.x;   // 512 threads
    if (t < BB*CIN_X) {
        int n = t >> 6, c = t & 63;
        float acc = d1b[c];
        #pragma unroll 4
        for (int e = 0; e < EE; e++) acc += embed[n*EE + e] * d1w[e*CIN_X + c];
        g_s1[t] = acc;
    }
    {
        int n = t >> 7, c = t & 127;
        float acc = d2b[c];
        #pragma unroll 4
        for (int e = 0; e < EE; e++) acc += context[n*EE + e] * d2w[e*COUT + c];
        g_s2[t] = acc;
    }
}

// ---------------------------------------------------------------------------
// Kernel 2: NCDHW fp32 x -> channels-last fp16 x and act=swish(x+s1)
// ---------------------------------------------------------------------------
__global__ void __launch_bounds__(256) cvt_x_kernel(const float* __restrict__ x)
{
    __shared__ float sm[64*133];
    const int h  = blockIdx.x;
    const int nd = blockIdx.y;
    const int n  = nd >> 3, d = nd & 7;
    const int tid = threadIdx.x;

    for (int i = tid; i < 64*128; i += 256) {
        int ci = i >> 7, w = i & 127;
        sm[ci*133 + w] = x[((size_t)(n*64 + ci)*8 + d)*HW + h*128 + w];
    }
    __syncthreads();
    size_t base = ((size_t)nd*128 + h) * 128 * 64;
    for (int i = tid; i < 64*128; i += 256) {
        int w = i >> 6, ci = i & 63;
        float v = sm[ci*133 + w];
        float a = swish_f(v + g_s1[n*64 + ci]);
        size_t o = base + (size_t)w*64 + ci;
        g_x[o] = __float2half(v);
        g_a[o] = __float2half(a);
    }
}

// ---------------------------------------------------------------------------
// Kernel 3: weight tiles, transposed (co-row, ci-col), fp16, SW128-swizzled
// ---------------------------------------------------------------------------
__global__ void wcvt_kernel(const float* __restrict__ w20,
                            const float* __restrict__ w21,
                            const float* __restrict__ resw,
                            const float* __restrict__ dwn)
{
    int c = blockIdx.x;     // 0..135
    int tid = threadIdx.x;
    for (int i = tid; i < 8192; i += 256) {
        int co = i >> 6, ci = i & 63;
        float v;
        if (c < 27) {
            v = w20[(co*64 + ci)*27 + c];
        } else if (c < 81) {
            int cc = c - 27; int tap = cc >> 1, half = cc & 1;
            v = w21[(co*128 + half*64 + ci)*27 + tap];
        } else if (c == 81) {
            v = resw[co*64 + ci];
        } else {
            int cc = c - 82; int tap = cc >> 1, half = cc & 1;
            v = dwn[(co*128 + half*64 + ci)*27 + tap];
        }
        uint32_t sw = swz(co*128 + ci*2);
        *(__half*)((char*)g_w + (size_t)c*16384 + sw) = __float2half(v);
    }
}

// ---------------------------------------------------------------------------
// Implicit-GEMM conv via single-pass fp16 mma.sync. M=128 px, N=128 co,
// K chunks of 64. 4-stage cp.async pipeline (128 KB smem).
// MODE 0: conv20  one (n,d,h) row         epi: +b20, swish, *s2 -> h1
// MODE 1: conv21  one (n,d,h) row + res   epi: +res_b, swish -> h2
// MODE 2: down    TWO oh rows packed (M = 2x64), stride-2 W/H  epi: +down_b -> out
// ---------------------------------------------------------------------------
#define STAGE_BYTES 32768   // A 16K | B 16K
#define NSTAGE 4
#define GEMM_SMEM   (NSTAGE*STAGE_BYTES)

template<int MODE>
__global__ void __launch_bounds__(256, 1) conv_mma(const float* __restrict__ bias,
                                                   float* __restrict__ outp)
{
    extern __shared__ __align__(1024) char smem[];
    constexpr int NCHUNK = (MODE == 0) ? 27 : (MODE == 1) ? 55 : 54;
    constexpr int WBASE  = (MODE == 0) ? 0  : (MODE == 1) ? 27 : 82;

    const uint32_t sb = smem_u32(smem);
    const int tid  = threadIdx.x;
    const int wid  = tid >> 5;
    const int lane = tid & 31;
    const int nd = blockIdx.y, n = nd >> 3, d = nd & 7;
    const int hq = blockIdx.x;   // h (MODE 0/1); oh-pair index (MODE 2)

    auto stage = [&](int c, int buf) {
        uint32_t aS = sb + buf*STAGE_BYTES;
        uint32_t bS = aS + 16384;
        const char* dummy = (const char*)g_w;

        if (MODE == 2) {
            int tap = c >> 1, half = c & 1;
            int kd = tap / 9, kh = (tap / 3) % 3, kw = tap % 3;
            int id = d + kd - 1;
            bool pvd = ((unsigned)id < 8u);
            const char* pl = (const char*)(g_h2 + ((size_t)(n*8 + id)*HW)*128 + half*64);
            #pragma unroll
            for (int t = 0; t < 4; t++) {
                int i = tid + t*256;
                int p = i >> 3, q = i & 7;
                int ohl = p >> 6, ow = p & 63;
                int oh = hq*2 + ohl;
                int iw = 2*ow + kw;
                int ih = oh*2 + kh;
                bool v = pvd && (ow < 63) && (oh < 63);
                size_t off = ((size_t)ih*128 + iw)*256 + q*16;
                cp_async16(aS + swz(p*128 + q*16), v ? pl + off : dummy, v);
            }
        } else {
            int ciStride = 64, kw = 1;
            bool pv = true;
            const char *src = nullptr;
            if (MODE == 1 && c == 54) {
                size_t pb = ((size_t)(nd*128 + hq)) * 128;
                src = (const char*)(g_x + pb*64);
            } else {
                int tap, half;
                if (MODE == 0) { tap = c; half = 0; ciStride = 64; }
                else           { tap = c >> 1; half = c & 1; ciStride = 128; }
                int kd = tap / 9, kh = (tap / 3) % 3;
                kw = tap % 3;
                int id = d + kd - 1;
                int ih = hq + kh - 1;
                pv = ((unsigned)id < 8u) && ((unsigned)ih < 128u);
                if (pv) {
                    size_t pb = ((size_t)((n*8 + id)*128 + ih)) * 128;
                    if (MODE == 0) src = (const char*)(g_a  + pb*64);
                    else           src = (const char*)(g_h1 + pb*128 + half*64);
                }
            }
            #pragma unroll
            for (int t = 0; t < 4; t++) {
                int i = tid + t*256;
                int p = i >> 3, q = i & 7;
                int iw = p + kw - 1;
                bool v = pv && ((unsigned)iw < 128u);
                size_t off = (size_t)iw * ciStride * 2 + q*16;
                cp_async16(aS + swz(p*128 + q*16), v ? src + off : dummy, v);
            }
        }
        const char* wS = (const char*)g_w + (size_t)(WBASE + c)*16384;
        #pragma unroll
        for (int t = 0; t < 4; t++) {
            int i = (tid + t*256)*16;
            cp_async16(bS + i, wS + i, true);
        }
    };

    // prologue: three chunks in flight
    stage(0, 0);
    asm volatile("cp.async.commit_group;");
    stage(1, 1);
    asm volatile("cp.async.commit_group;");
    stage(2, 2);
    asm volatile("cp.async.commit_group;");

    const int m0 = (wid & 3) * 32;
    const int n0 = (wid >> 2) * 64;
    float acc[2][8][4];
    #pragma unroll
    for (int a = 0; a < 2; a++)
        #pragma unroll
        for (int b = 0; b < 8; b++)
            #pragma unroll
            for (int q = 0; q < 4; q++) acc[a][b][q] = 0.f;

    int bufc = 0;  // c % 4
    for (int c = 0; c < NCHUNK; c++) {
        asm volatile("cp.async.wait_group 2;" ::: "memory");
        __syncthreads();
        // stage chunk c+3 into buffer (c+3)%4 (freed: compute of c-1 done)
        int bufn = bufc + 3; if (bufn >= NSTAGE) bufn -= NSTAGE;
        if (c + 3 < NCHUNK) stage(c + 3, bufn);
        asm volatile("cp.async.commit_group;");

        uint32_t aS = sb + bufc*STAGE_BYTES;
        uint32_t bS = aS + 16384;
        const int sub = lane >> 3, r = lane & 7;

        #pragma unroll
        for (int kk = 0; kk < 4; kk++) {
            const int k0b = kk*32;
            uint32_t aF[2][4], bF[4][4];
            #pragma unroll
            for (int fm = 0; fm < 2; fm++) {
                uint32_t so = swz((m0 + fm*16 + (sub & 1)*8 + r)*128 + k0b + (sub >> 1)*16);
                ldm4(aF[fm], aS + so);
            }
            #pragma unroll
            for (int nb = 0; nb < 4; nb++) {
                uint32_t so = swz((n0 + nb*16 + (sub >> 1)*8 + r)*128 + k0b + (sub & 1)*16);
                ldm4(bF[nb], bS + so);
            }
            #pragma unroll
            for (int fm = 0; fm < 2; fm++) {
                #pragma unroll
                for (int j = 0; j < 8; j++) {
                    mma16816(acc[fm][j], aF[fm], &bF[j >> 1][(j & 1)*2]);
                }
            }
        }
        bufc++; if (bufc >= NSTAGE) bufc = 0;
    }
    asm volatile("cp.async.wait_all;" ::: "memory");

    // ---- epilogue ----
    const size_t rowBase = (size_t)(nd*128 + hq) * 128;
    #pragma unroll
    for (int fm = 0; fm < 2; fm++) {
        #pragma unroll
        for (int j = 0; j < 8; j++) {
            int c0 = n0 + j*8 + (lane & 3)*2;
            int r0 = m0 + fm*16 + (lane >> 2);
            float b0v = bias[c0], b1v = bias[c0 + 1];
            #pragma unroll
            for (int rr = 0; rr < 2; rr++) {
                int row = r0 + rr*8;
                float v0 = acc[fm][j][rr*2 + 0] + b0v;
                float v1 = acc[fm][j][rr*2 + 1] + b1v;
                if (MODE == 2) {
                    int ohl = row >> 6, ow = row & 63;
                    int oh = hq*2 + ohl;
                    if (ow < OW && oh < OH) {
                        size_t ob = ((size_t)(n*128 + c0)*8 + d)*(OH*OW) + oh*OW + ow;
                        outp[ob] = v0;
                        outp[ob + (size_t)8*(OH*OW)] = v1;
                    }
                } else {
                    if (MODE == 0) {
                        v0 = swish_f(v0) * g_s2[n*128 + c0];
                        v1 = swish_f(v1) * g_s2[n*128 + c0 + 1];
                    } else {
                        v0 = swish_f(v0);
                        v1 = swish_f(v1);
                    }
                    __half h0 = __float2half(v0);
                    __half h1 = __float2half(v1);
                    uint32_t hp = (uint32_t)__half_as_ushort(h1) << 16 |
                                  __half_as_ushort(h0);
                    size_t ob = (rowBase + row)*128 + c0;
                    if (MODE == 0) *(uint32_t*)(g_h1 + ob) = hp;
                    else           *(uint32_t*)(g_h2 + ob) = hp;
                }
            }
        }
    }
}

// ---------------------------------------------------------------------------
extern "C" void kernel_launch(void* const* d_in, const int* in_sizes, int n_in,
                              void* d_out, int out_size)
{
    const float* x       = (const float*)d_in[0];
    const float* embed   = (const float*)d_in[1];
    const float* context = (const float*)d_in[2];
    const float* w20     = (const float*)d_in[3];
    const float* b20     = (const float*)d_in[4];
    const float* w21     = (const float*)d_in[5];
    const float* d1_w    = (const float*)d_in[6];
    const float* d1_b    = (const float*)d_in[7];
    const float* d2_w    = (const float*)d_in[8];
    const float* d2_b    = (const float*)d_in[9];
    const float* res_w   = (const float*)d_in[10];
    const float* res_b   = (const float*)d_in[11];
    const float* down_w  = (const float*)d_in[12];
    const float* down_b  = (const float*)d_in[13];
    float* out = (float*)d_out;

    cudaFuncSetAttribute(conv_mma<0>, cudaFuncAttributeMaxDynamicSharedMemorySize, GEMM_SMEM);
    cudaFuncSetAttribute(conv_mma<1>, cudaFuncAttributeMaxDynamicSharedMemorySize, GEMM_SMEM);
    cudaFuncSetAttribute(conv_mma<2>, cudaFuncAttributeMaxDynamicSharedMemorySize, GEMM_SMEM);

    s_kernel<<<1, 512>>>(embed, context, d1_w, d1_b, d2_w, d2_b);
    cvt_x_kernel<<<dim3(HH, BB*DD), 256>>>(x);
    wcvt_kernel<<<136, 256>>>(w20, w21, res_w, down_w);

    conv_mma<0><<<dim3(HH, BB*DD), 256, GEMM_SMEM>>>(b20,    nullptr);
    conv_mma<1><<<dim3(HH, BB*DD), 256, GEMM_SMEM>>>(res_b,  nullptr);
    conv_mma<2><<<dim3(32, BB*DD), 256, GEMM_SMEM>>>(down_b, out);
}

// round 6
// speedup vs baseline: 10.6943x; 1.1740x over previous
#include <cuda_runtime.h>
#include <cuda_fp16.h>
#include <cstdint>

// Problem constants
#define BB 4
#define CIN_X 64
#define COUT 128
#define DD 8
#define HH 128
#define WW 128
#define EE 256
#define OH 63
#define OW 63
#define HW (HH*WW)

// ---------------------------------------------------------------------------
// Device-global scratch. Channels-last (NDHWC) fp16 tensors.
// ---------------------------------------------------------------------------
__device__ float g_s1[BB*CIN_X];
__device__ float g_s2[BB*COUT];
__device__ __half g_x[BB*DD*HH*WW*64];            // x (for residual tap)
__device__ __half g_a[BB*DD*HH*WW*64];            // swish(x+s1)
__device__ __half g_h1[(size_t)BB*DD*HH*WW*128];  // after conv20 epi
__device__ __half g_h2[(size_t)BB*DD*HH*WW*128];  // after conv21 epi
// Pre-transposed + pre-swizzled weight tiles: 136 chunks x (128co x 64ci) fp16
// [0,27) conv20 taps; [27,81) conv21 (tap,cihalf); 81 res; [82,136) down
__device__ __half g_w[136*8192];

__device__ __forceinline__ float swish_f(float v) {
    return v / (1.f + __expf(-v));
}

__device__ __forceinline__ uint32_t smem_u32(const void* p) {
    uint32_t a;
    asm("{ .reg .u64 t; cvta.to.shared.u64 t, %1; cvt.u32.u64 %0, t; }" : "=r"(a) : "l"(p));
    return a;
}

__device__ __forceinline__ uint32_t swz(uint32_t off) {
    return off ^ ((off >> 3) & 0x70);
}

__device__ __forceinline__ void cp_async16(uint32_t dst, const void* src, bool valid) {
    int sz = valid ? 16 : 0;
    asm volatile("cp.async.cg.shared.global [%0], [%1], 16, %2;"
                 :: "r"(dst), "l"(src), "r"(sz));
}

__device__ __forceinline__ void ldm4(uint32_t* r, uint32_t addr) {
    asm volatile("ldmatrix.sync.aligned.m8n8.x4.shared.b16 {%0,%1,%2,%3}, [%4];"
                 : "=r"(r[0]), "=r"(r[1]), "=r"(r[2]), "=r"(r[3]) : "r"(addr));
}

__device__ __forceinline__ void mma16816(float* d, const uint32_t* a, const uint32_t* b) {
    asm volatile(
        "mma.sync.aligned.m16n8k16.row.col.f32.f16.f16.f32 "
        "{%0,%1,%2,%3}, {%4,%5,%6,%7}, {%8,%9}, {%0,%1,%2,%3};"
        : "+f"(d[0]), "+f"(d[1]), "+f"(d[2]), "+f"(d[3])
        : "r"(a[0]), "r"(a[1]), "r"(a[2]), "r"(a[3]), "r"(b[0]), "r"(b[1]));
}

// ---------------------------------------------------------------------------
// Kernel 1: s1 = embed @ d1_w + d1_b; s2 = context @ d2_w + d2_b
// ---------------------------------------------------------------------------
__global__ void s_kernel(const float* __restrict__ embed,
                         const float* __restrict__ context,
                         const float* __restrict__ d1w, const float* __restrict__ d1b,
                         const float* __restrict__ d2w, const float* __restrict__ d2b)
{
    int t = threadIdx.x;   // 512 threads
    if (t < BB*CIN_X) {
        int n = t >> 6, c = t & 63;
        float acc = d1b[c];
        #pragma unroll 4
        for (int e = 0; e < EE; e++) acc += embed[n*EE + e] * d1w[e*CIN_X + c];
        g_s1[t] = acc;
    }
    {
        int n = t >> 7, c = t & 127;
        float acc = d2b[c];
        #pragma unroll 4
        for (int e = 0; e < EE; e++) acc += context[n*EE + e] * d2w[e*COUT + c];
        g_s2[t] = acc;
    }
}

// ---------------------------------------------------------------------------
// Kernel 2: NCDHW fp32 x -> channels-last fp16 x and act=swish(x+s1)
// ---------------------------------------------------------------------------
__global__ void __launch_bounds__(256) cvt_x_kernel(const float* __restrict__ x)
{
    __shared__ float sm[64*133];
    const int h  = blockIdx.x;
    const int nd = blockIdx.y;
    const int n  = nd >> 3, d = nd & 7;
    const int tid = threadIdx.x;

    for (int i = tid; i < 64*128; i += 256) {
        int ci = i >> 7, w = i & 127;
        sm[ci*133 + w] = x[((size_t)(n*64 + ci)*8 + d)*HW + h*128 + w];
    }
    __syncthreads();
    size_t base = ((size_t)nd*128 + h) * 128 * 64;
    for (int i = tid; i < 64*128; i += 256) {
        int w = i >> 6, ci = i & 63;
        float v = sm[ci*133 + w];
        float a = swish_f(v + g_s1[n*64 + ci]);
        size_t o = base + (size_t)w*64 + ci;
        g_x[o] = __float2half(v);
        g_a[o] = __float2half(a);
    }
}

// ---------------------------------------------------------------------------
// Kernel 3: weight tiles, transposed (co-row, ci-col), fp16, SW128-swizzled
// ---------------------------------------------------------------------------
__global__ void wcvt_kernel(const float* __restrict__ w20,
                            const float* __restrict__ w21,
                            const float* __restrict__ resw,
                            const float* __restrict__ dwn)
{
    int c = blockIdx.x;     // 0..135
    int tid = threadIdx.x;
    for (int i = tid; i < 8192; i += 256) {
        int co = i >> 6, ci = i & 63;
        float v;
        if (c < 27) {
            v = w20[(co*64 + ci)*27 + c];
        } else if (c < 81) {
            int cc = c - 27; int tap = cc >> 1, half = cc & 1;
            v = w21[(co*128 + half*64 + ci)*27 + tap];
        } else if (c == 81) {
            v = resw[co*64 + ci];
        } else {
            int cc = c - 82; int tap = cc >> 1, half = cc & 1;
            v = dwn[(co*128 + half*64 + ci)*27 + tap];
        }
        uint32_t sw = swz(co*128 + ci*2);
        *(__half*)((char*)g_w + (size_t)c*16384 + sw) = __float2half(v);
    }
}

// ---------------------------------------------------------------------------
// Implicit-GEMM conv, single-pass fp16 mma.sync.
// CTA tile: M=128 px x N=64 co (co half selected by blockIdx.z) -> 2 CTA/SM.
// Warp tile 32x32 (8 warps = 4M x 2N). K chunks of 64. 4-stage cp.async.
// MODE 0: conv20  one (n,d,h) row         epi: +b20, swish, *s2 -> h1
// MODE 1: conv21  one (n,d,h) row + res   epi: +res_b, swish -> h2
// MODE 2: down    TWO oh rows packed (M = 2x64), stride-2 W/H  epi: +down_b -> out
// ---------------------------------------------------------------------------
#define STAGE_BYTES 24576   // A 16K | B 8K
#define NSTAGE 4
#define GEMM_SMEM   (NSTAGE*STAGE_BYTES)

template<int MODE>
__global__ void __launch_bounds__(256, 2) conv_mma(const float* __restrict__ bias,
                                                   float* __restrict__ outp)
{
    extern __shared__ __align__(1024) char smem[];
    constexpr int NCHUNK = (MODE == 0) ? 27 : (MODE == 1) ? 55 : 54;
    constexpr int WBASE  = (MODE == 0) ? 0  : (MODE == 1) ? 27 : 82;

    const uint32_t sb = smem_u32(smem);
    const int tid  = threadIdx.x;
    const int wid  = tid >> 5;
    const int lane = tid & 31;
    const int nd = blockIdx.y, n = nd >> 3, d = nd & 7;
    const int hq = blockIdx.x;       // h (MODE 0/1); oh-pair index (MODE 2)
    const int cob = blockIdx.z;      // co half: 0 or 1

    auto stage = [&](int c, int buf) {
        uint32_t aS = sb + buf*STAGE_BYTES;
        uint32_t bS = aS + 16384;
        const char* dummy = (const char*)g_w;

        if (MODE == 2) {
            int tap = c >> 1, half = c & 1;
            int kd = tap / 9, kh = (tap / 3) % 3, kw = tap % 3;
            int id = d + kd - 1;
            bool pvd = ((unsigned)id < 8u);
            const char* pl = (const char*)(g_h2 + ((size_t)(n*8 + id)*HW)*128 + half*64);
            #pragma unroll
            for (int t = 0; t < 4; t++) {
                int i = tid + t*256;
                int p = i >> 3, q = i & 7;
                int ohl = p >> 6, ow = p & 63;
                int oh = hq*2 + ohl;
                int iw = 2*ow + kw;
                int ih = oh*2 + kh;
                bool v = pvd && (ow < 63) && (oh < 63);
                size_t off = ((size_t)ih*128 + iw)*256 + q*16;
                cp_async16(aS + swz(p*128 + q*16), v ? pl + off : dummy, v);
            }
        } else {
            int ciStride = 64, kw = 1;
            bool pv = true;
            const char *src = nullptr;
            if (MODE == 1 && c == 54) {
                size_t pb = ((size_t)(nd*128 + hq)) * 128;
                src = (const char*)(g_x + pb*64);
            } else {
                int tap, half;
                if (MODE == 0) { tap = c; half = 0; ciStride = 64; }
                else           { tap = c >> 1; half = c & 1; ciStride = 128; }
                int kd = tap / 9, kh = (tap / 3) % 3;
                kw = tap % 3;
                int id = d + kd - 1;
                int ih = hq + kh - 1;
                pv = ((unsigned)id < 8u) && ((unsigned)ih < 128u);
                if (pv) {
                    size_t pb = ((size_t)((n*8 + id)*128 + ih)) * 128;
                    if (MODE == 0) src = (const char*)(g_a  + pb*64);
                    else           src = (const char*)(g_h1 + pb*128 + half*64);
                }
            }
            #pragma unroll
            for (int t = 0; t < 4; t++) {
                int i = tid + t*256;
                int p = i >> 3, q = i & 7;
                int iw = p + kw - 1;
                bool v = pv && ((unsigned)iw < 128u);
                size_t off = (size_t)iw * ciStride * 2 + q*16;
                cp_async16(aS + swz(p*128 + q*16), v ? src + off : dummy, v);
            }
        }
        // B: this CTA's 64-co half (8 KB). Swizzle pattern is 1KB-periodic,
        // so the half-tile copies verbatim.
        const char* wS = (const char*)g_w + (size_t)(WBASE + c)*16384 + cob*8192;
        #pragma unroll
        for (int t = 0; t < 2; t++) {
            int i = (tid + t*256)*16;
            cp_async16(bS + i, wS + i, true);
        }
    };

    // prologue: three chunks in flight
    stage(0, 0);
    asm volatile("cp.async.commit_group;");
    stage(1, 1);
    asm volatile("cp.async.commit_group;");
    stage(2, 2);
    asm volatile("cp.async.commit_group;");

    const int m0 = (wid & 3) * 32;
    const int n0 = (wid >> 2) * 32;
    float acc[2][4][4];
    #pragma unroll
    for (int a = 0; a < 2; a++)
        #pragma unroll
        for (int b = 0; b < 4; b++)
            #pragma unroll
            for (int q = 0; q < 4; q++) acc[a][b][q] = 0.f;

    int bufc = 0;  // c % 4
    for (int c = 0; c < NCHUNK; c++) {
        asm volatile("cp.async.wait_group 2;" ::: "memory");
        __syncthreads();
        int bufn = bufc + 3; if (bufn >= NSTAGE) bufn -= NSTAGE;
        if (c + 3 < NCHUNK) stage(c + 3, bufn);
        asm volatile("cp.async.commit_group;");

        uint32_t aS = sb + bufc*STAGE_BYTES;
        uint32_t bS = aS + 16384;
        const int sub = lane >> 3, r = lane & 7;

        #pragma unroll
        for (int kk = 0; kk < 4; kk++) {
            const int k0b = kk*32;
            uint32_t aF[2][4], bF[2][4];
            #pragma unroll
            for (int fm = 0; fm < 2; fm++) {
                uint32_t so = swz((m0 + fm*16 + (sub & 1)*8 + r)*128 + k0b + (sub >> 1)*16);
                ldm4(aF[fm], aS + so);
            }
            #pragma unroll
            for (int nb = 0; nb < 2; nb++) {
                uint32_t so = swz((n0 + nb*16 + (sub >> 1)*8 + r)*128 + k0b + (sub & 1)*16);
                ldm4(bF[nb], bS + so);
            }
            #pragma unroll
            for (int fm = 0; fm < 2; fm++) {
                #pragma unroll
                for (int j = 0; j < 4; j++) {
                    mma16816(acc[fm][j], aF[fm], &bF[j >> 1][(j & 1)*2]);
                }
            }
        }
        bufc++; if (bufc >= NSTAGE) bufc = 0;
    }
    asm volatile("cp.async.wait_all;" ::: "memory");

    // ---- epilogue ----
    const size_t rowBase = (size_t)(nd*128 + hq) * 128;
    #pragma unroll
    for (int fm = 0; fm < 2; fm++) {
        #pragma unroll
        for (int j = 0; j < 4; j++) {
            int c0 = cob*64 + n0 + j*8 + (lane & 3)*2;
            int r0 = m0 + fm*16 + (lane >> 2);
            float b0v = bias[c0], b1v = bias[c0 + 1];
            #pragma unroll
            for (int rr = 0; rr < 2; rr++) {
                int row = r0 + rr*8;
                float v0 = acc[fm][j][rr*2 + 0] + b0v;
                float v1 = acc[fm][j][rr*2 + 1] + b1v;
                if (MODE == 2) {
                    int ohl = row >> 6, ow = row & 63;
                    int oh = hq*2 + ohl;
                    if (ow < OW && oh < OH) {
                        size_t ob = ((size_t)(n*128 + c0)*8 + d)*(OH*OW) + oh*OW + ow;
                        outp[ob] = v0;
                        outp[ob + (size_t)8*(OH*OW)] = v1;
                    }
                } else {
                    if (MODE == 0) {
                        v0 = swish_f(v0) * g_s2[n*128 + c0];
                        v1 = swish_f(v1) * g_s2[n*128 + c0 + 1];
                    } else {
                        v0 = swish_f(v0);
                        v1 = swish_f(v1);
                    }
                    __half h0 = __float2half(v0);
                    __half h1 = __float2half(v1);
                    uint32_t hp = (uint32_t)__half_as_ushort(h1) << 16 |
                                  __half_as_ushort(h0);
                    size_t ob = (rowBase + row)*128 + c0;
                    if (MODE == 0) *(uint32_t*)(g_h1 + ob) = hp;
                    else           *(uint32_t*)(g_h2 + ob) = hp;
                }
            }
        }
    }
}

// ---------------------------------------------------------------------------
extern "C" void kernel_launch(void* const* d_in, const int* in_sizes, int n_in,
                              void* d_out, int out_size)
{
    const float* x       = (const float*)d_in[0];
    const float* embed   = (const float*)d_in[1];
    const float* context = (const float*)d_in[2];
    const float* w20     = (const float*)d_in[3];
    const float* b20     = (const float*)d_in[4];
    const float* w21     = (const float*)d_in[5];
    const float* d1_w    = (const float*)d_in[6];
    const float* d1_b    = (const float*)d_in[7];
    const float* d2_w    = (const float*)d_in[8];
    const float* d2_b    = (const float*)d_in[9];
    const float* res_w   = (const float*)d_in[10];
    const float* res_b   = (const float*)d_in[11];
    const float* down_w  = (const float*)d_in[12];
    const float* down_b  = (const float*)d_in[13];
    float* out = (float*)d_out;

    cudaFuncSetAttribute(conv_mma<0>, cudaFuncAttributeMaxDynamicSharedMemorySize, GEMM_SMEM);
    cudaFuncSetAttribute(conv_mma<1>, cudaFuncAttributeMaxDynamicSharedMemorySize, GEMM_SMEM);
    cudaFuncSetAttribute(conv_mma<2>, cudaFuncAttributeMaxDynamicSharedMemorySize, GEMM_SMEM);

    s_kernel<<<1, 512>>>(embed, context, d1_w, d1_b, d2_w, d2_b);
    cvt_x_kernel<<<dim3(HH, BB*DD), 256>>>(x);
    wcvt_kernel<<<136, 256>>>(w20, w21, res_w, down_w);

    conv_mma<0><<<dim3(HH, BB*DD, 2), 256, GEMM_SMEM>>>(b20,    nullptr);
    conv_mma<1><<<dim3(HH, BB*DD, 2), 256, GEMM_SMEM>>>(res_b,  nullptr);
    conv_mma<2><<<dim3(32, BB*DD, 2), 256, GEMM_SMEM>>>(down_b, out);
}

// round 7
// speedup vs baseline: 11.9797x; 1.1202x over previous
#include <cuda_runtime.h>
#include <cuda_fp16.h>
#include <cstdint>

// Problem constants
#define BB 4
#define CIN_X 64
#define COUT 128
#define DD 8
#define HH 128
#define WW 128
#define EE 256
#define OH 63
#define OW 63
#define HW (HH*WW)

// ---------------------------------------------------------------------------
// Device-global scratch. Channels-last (NDHWC) fp16 tensors.
// ---------------------------------------------------------------------------
__device__ float g_s1[BB*CIN_X];
__device__ float g_s2[BB*COUT];
__device__ __half g_x[BB*DD*HH*WW*64];            // x (for residual tap)
__device__ __half g_a[BB*DD*HH*WW*64];            // swish(x+s1)
__device__ __half g_h1[(size_t)BB*DD*HH*WW*128];  // after conv20 epi
__device__ __half g_h2[(size_t)BB*DD*HH*WW*128];  // after conv21 epi
// Pre-transposed + pre-swizzled weight tiles: 136 chunks x (128co x 64ci) fp16
// [0,27) conv20 taps; [27,81) conv21 (tap,cihalf); 81 res; [82,136) down
__device__ __half g_w[136*8192];

__device__ __forceinline__ float swish_f(float v) {
    return v / (1.f + __expf(-v));
}

__device__ __forceinline__ uint32_t smem_u32(const void* p) {
    uint32_t a;
    asm("{ .reg .u64 t; cvta.to.shared.u64 t, %1; cvt.u32.u64 %0, t; }" : "=r"(a) : "l"(p));
    return a;
}

__device__ __forceinline__ uint32_t swz(uint32_t off) {
    return off ^ ((off >> 3) & 0x70);
}

__device__ __forceinline__ void cp_async16(uint32_t dst, const void* src, bool valid) {
    int sz = valid ? 16 : 0;
    asm volatile("cp.async.cg.shared.global [%0], [%1], 16, %2;"
                 :: "r"(dst), "l"(src), "r"(sz));
}

__device__ __forceinline__ void ldm4(uint32_t* r, uint32_t addr) {
    asm volatile("ldmatrix.sync.aligned.m8n8.x4.shared.b16 {%0,%1,%2,%3}, [%4];"
                 : "=r"(r[0]), "=r"(r[1]), "=r"(r[2]), "=r"(r[3]) : "r"(addr));
}

__device__ __forceinline__ void mma16816(float* d, const uint32_t* a, const uint32_t* b) {
    asm volatile(
        "mma.sync.aligned.m16n8k16.row.col.f32.f16.f16.f32 "
        "{%0,%1,%2,%3}, {%4,%5,%6,%7}, {%8,%9}, {%0,%1,%2,%3};"
        : "+f"(d[0]), "+f"(d[1]), "+f"(d[2]), "+f"(d[3])
        : "r"(a[0]), "r"(a[1]), "r"(a[2]), "r"(a[3]), "r"(b[0]), "r"(b[1]));
}

// ---------------------------------------------------------------------------
// Kernel 1: s1 = embed @ d1_w + d1_b; s2 = context @ d2_w + d2_b
// ---------------------------------------------------------------------------
__global__ void s_kernel(const float* __restrict__ embed,
                         const float* __restrict__ context,
                         const float* __restrict__ d1w, const float* __restrict__ d1b,
                         const float* __restrict__ d2w, const float* __restrict__ d2b)
{
    int t = threadIdx.x;   // 512 threads
    if (t < BB*CIN_X) {
        int n = t >> 6, c = t & 63;
        float acc = d1b[c];
        #pragma unroll 4
        for (int e = 0; e < EE; e++) acc += embed[n*EE + e] * d1w[e*CIN_X + c];
        g_s1[t] = acc;
    }
    {
        int n = t >> 7, c = t & 127;
        float acc = d2b[c];
        #pragma unroll 4
        for (int e = 0; e < EE; e++) acc += context[n*EE + e] * d2w[e*COUT + c];
        g_s2[t] = acc;
    }
}

// ---------------------------------------------------------------------------
// Kernel 2: NCDHW fp32 x -> channels-last fp16 x and act=swish(x+s1)
// ---------------------------------------------------------------------------
__global__ void __launch_bounds__(256) cvt_x_kernel(const float* __restrict__ x)
{
    __shared__ float sm[64*133];
    const int h  = blockIdx.x;
    const int nd = blockIdx.y;
    const int n  = nd >> 3, d = nd & 7;
    const int tid = threadIdx.x;

    for (int i = tid; i < 64*128; i += 256) {
        int ci = i >> 7, w = i & 127;
        sm[ci*133 + w] = x[((size_t)(n*64 + ci)*8 + d)*HW + h*128 + w];
    }
    __syncthreads();
    size_t base = ((size_t)nd*128 + h) * 128 * 64;
    for (int i = tid; i < 64*128; i += 256) {
        int w = i >> 6, ci = i & 63;
        float v = sm[ci*133 + w];
        float a = swish_f(v + g_s1[n*64 + ci]);
        size_t o = base + (size_t)w*64 + ci;
        g_x[o] = __float2half(v);
        g_a[o] = __float2half(a);
    }
}

// ---------------------------------------------------------------------------
// Kernel 3: weight tiles, transposed (co-row, ci-col), fp16, SW128-swizzled
// ---------------------------------------------------------------------------
__global__ void wcvt_kernel(const float* __restrict__ w20,
                            const float* __restrict__ w21,
                            const float* __restrict__ resw,
                            const float* __restrict__ dwn)
{
    int c = blockIdx.x;     // 0..135
    int tid = threadIdx.x;
    for (int i = tid; i < 8192; i += 256) {
        int co = i >> 6, ci = i & 63;
        float v;
        if (c < 27) {
            v = w20[(co*64 + ci)*27 + c];
        } else if (c < 81) {
            int cc = c - 27; int tap = cc >> 1, half = cc & 1;
            v = w21[(co*128 + half*64 + ci)*27 + tap];
        } else if (c == 81) {
            v = resw[co*64 + ci];
        } else {
            int cc = c - 82; int tap = cc >> 1, half = cc & 1;
            v = dwn[(co*128 + half*64 + ci)*27 + tap];
        }
        uint32_t sw = swz(co*128 + ci*2);
        *(__half*)((char*)g_w + (size_t)c*16384 + sw) = __float2half(v);
    }
}

// ---------------------------------------------------------------------------
// Implicit-GEMM conv, single-pass fp16 mma.sync.
// CTA tile: M=128 px x N=64 co (co half via blockIdx.z) -> 2 CTA/SM.
// Warp tile 32x32 (8 warps = 4M x 2N).
// MODE 0: conv20. 9 plane-chunks (kd,kh), each K=192 (3 kw-taps from one
//         staged 130-row A buffer). epi: +b20, swish, *s2 -> h1
// MODE 1: conv21. 18 plane-half-chunks + 1 residual chunk. epi: +res_b, swish -> h2
// MODE 2: down. 54 per-tap chunks (round-6 scheme), M = 2 oh-rows x 64 ow,
//         stride-2 W/H. epi: +down_b -> out (NCDHW fp32)
// ---------------------------------------------------------------------------
// MODE 0/1 stage: A 17408 (132 rows x 128B; rows 0..129 = iw -1..128) | B 24576 (3 taps)
// MODE 2   stage: A 16384 (128 px rows) | B 8192 (1 tap)
#define STAGE_P   41984
#define STAGE_T   24576
#define NSTAGE_T  4

template<int MODE>
__global__ void __launch_bounds__(256, 2) conv_mma(const float* __restrict__ bias,
                                                   float* __restrict__ outp)
{
    extern __shared__ __align__(1024) char smem[];
    constexpr int NCHUNK = (MODE == 0) ? 9 : (MODE == 1) ? 19 : 54;

    const uint32_t sb = smem_u32(smem);
    const int tid  = threadIdx.x;
    const int wid  = tid >> 5;
    const int lane = tid & 31;
    const int nd = blockIdx.y, n = nd >> 3, d = nd & 7;
    const int hq = blockIdx.x;       // h (MODE 0/1); oh-pair index (MODE 2)
    const int cob = blockIdx.z;      // co half: 0 or 1

    const int m0 = (wid & 3) * 32;
    const int n0 = (wid >> 2) * 32;
    const int sub = lane >> 3, rl = lane & 7;

    float acc[2][4][4];
    #pragma unroll
    for (int a = 0; a < 2; a++)
        #pragma unroll
        for (int b = 0; b < 4; b++)
            #pragma unroll
            for (int q = 0; q < 4; q++) acc[a][b][q] = 0.f;

    if constexpr (MODE == 2) {
        // ------------------- per-tap scheme (round 6) -------------------
        auto stage = [&](int c, int buf) {
            uint32_t aS = sb + buf*STAGE_T;
            uint32_t bS = aS + 16384;
            const char* dummy = (const char*)g_w;
            int tap = c >> 1, half = c & 1;
            int kd = tap / 9, kh = (tap / 3) % 3, kw = tap % 3;
            int id = d + kd - 1;
            bool pvd = ((unsigned)id < 8u);
            const char* pl = (const char*)(g_h2 + ((size_t)(n*8 + id)*HW)*128 + half*64);
            #pragma unroll
            for (int t = 0; t < 4; t++) {
                int i = tid + t*256;
                int p = i >> 3, q = i & 7;
                int ohl = p >> 6, ow = p & 63;
                int oh = hq*2 + ohl;
                int iw = 2*ow + kw;
                int ih = oh*2 + kh;
                bool v = pvd && (ow < 63) && (oh < 63);
                size_t off = ((size_t)ih*128 + iw)*256 + q*16;
                cp_async16(aS + swz(p*128 + q*16), v ? pl + off : dummy, v);
            }
            const char* wS = (const char*)g_w + (size_t)(82 + c)*16384 + cob*8192;
            #pragma unroll
            for (int t = 0; t < 2; t++) {
                int i = (tid + t*256)*16;
                cp_async16(bS + i, wS + i, true);
            }
        };

        stage(0, 0);
        asm volatile("cp.async.commit_group;");
        stage(1, 1);
        asm volatile("cp.async.commit_group;");
        stage(2, 2);
        asm volatile("cp.async.commit_group;");

        int bufc = 0;
        for (int c = 0; c < NCHUNK; c++) {
            asm volatile("cp.async.wait_group 2;" ::: "memory");
            __syncthreads();
            int bufn = bufc + 3; if (bufn >= NSTAGE_T) bufn -= NSTAGE_T;
            if (c + 3 < NCHUNK) stage(c + 3, bufn);
            asm volatile("cp.async.commit_group;");

            uint32_t aS = sb + bufc*STAGE_T;
            uint32_t bS = aS + 16384;
            #pragma unroll
            for (int kk = 0; kk < 4; kk++) {
                const int k0b = kk*32;
                uint32_t aF[2][4], bF[2][4];
                #pragma unroll
                for (int fm = 0; fm < 2; fm++) {
                    uint32_t so = swz((m0 + fm*16 + (sub & 1)*8 + rl)*128 + k0b + (sub >> 1)*16);
                    ldm4(aF[fm], aS + so);
                }
                #pragma unroll
                for (int nb = 0; nb < 2; nb++) {
                    uint32_t so = swz((n0 + nb*16 + (sub >> 1)*8 + rl)*128 + k0b + (sub & 1)*16);
                    ldm4(bF[nb], bS + so);
                }
                #pragma unroll
                for (int fm = 0; fm < 2; fm++)
                    #pragma unroll
                    for (int j = 0; j < 4; j++)
                        mma16816(acc[fm][j], aF[fm], &bF[j >> 1][(j & 1)*2]);
            }
            bufc++; if (bufc >= NSTAGE_T) bufc = 0;
        }
        asm volatile("cp.async.wait_all;" ::: "memory");
    } else {
        // ------------------- plane-chunk scheme -------------------
        auto stage = [&](int c, int buf) {
            uint32_t aS = sb + buf*STAGE_P;
            uint32_t bS = aS + 17408;
            const char* dummy = (const char*)g_w;
            bool isRes = (MODE == 1) && (c == 18);
            if (!isRes) {
                int pc, half, srcStride;
                if (MODE == 0) { pc = c; half = 0; srcStride = 128; }
                else           { pc = c >> 1; half = c & 1; srcStride = 256; }
                int kd = pc / 3, kh = pc % 3;
                int id = d + kd - 1;
                int ih = hq + kh - 1;
                bool pv = ((unsigned)id < 8u) && ((unsigned)ih < 128u);
                const char* src = nullptr;
                if (pv) {
                    size_t pb = ((size_t)((n*8 + id)*128 + ih)) * 128;
                    if (MODE == 0) src = (const char*)(g_a  + pb*64);
                    else           src = (const char*)(g_h1 + pb*128 + half*64);
                }
                // A: rows 0..129 <-> iw -1..128 (zero-filled at halo/invalid)
                for (int i = tid; i < 1040; i += 256) {
                    int r = i >> 3, q = i & 7;
                    int iw = r - 1;
                    bool v = pv && ((unsigned)iw < 128u);
                    cp_async16(aS + swz(r*128 + q*16),
                               v ? src + (size_t)iw*srcStride + q*16 : dummy, v);
                }
                // B: 3 kw taps, each 8KB (this CTA's co-half)
                #pragma unroll
                for (int t = 0; t < 6; t++) {
                    int i = tid + t*256;      // 1536 16B-units
                    int kw = i >> 9, j = i & 511;
                    int wchunk = (MODE == 0) ? (pc*3 + kw)
                                             : 27 + ((pc*3 + kw)*2 + half);
                    const char* wS = (const char*)g_w + (size_t)wchunk*16384 + cob*8192;
                    cp_async16(bS + i*16, wS + j*16, true);
                }
            } else {
                // residual 1x1x1 tap: A rows 0..127 <-> pixel p of x_cl
                const char* src = (const char*)(g_x + ((size_t)(nd*128 + hq))*128*64);
                #pragma unroll
                for (int t = 0; t < 4; t++) {
                    int i = tid + t*256;
                    int r = i >> 3, q = i & 7;
                    cp_async16(aS + swz(r*128 + q*16), src + (size_t)r*128 + q*16, true);
                }
                const char* wS = (const char*)g_w + (size_t)81*16384 + cob*8192;
                #pragma unroll
                for (int t = 0; t < 2; t++) {
                    int i = (tid + t*256)*16;
                    cp_async16(bS + i, wS + i, true);
                }
            }
        };

        stage(0, 0);
        asm volatile("cp.async.commit_group;");

        for (int c = 0; c < NCHUNK; c++) {
            asm volatile("cp.async.wait_group 0;" ::: "memory");
            __syncthreads();
            if (c + 1 < NCHUNK) stage(c + 1, (c + 1) & 1);
            asm volatile("cp.async.commit_group;");

            uint32_t aS = sb + (c & 1)*STAGE_P;
            uint32_t bS = aS + 17408;
            bool isRes = (MODE == 1) && (c == 18);

            auto doTap = [&](int tap) {
                #pragma unroll
                for (int kk = 0; kk < 4; kk++) {
                    const int k0b = kk*32;
                    uint32_t aF[2][4], bF[2][4];
                    #pragma unroll
                    for (int fm = 0; fm < 2; fm++) {
                        uint32_t row = m0 + fm*16 + (sub & 1)*8 + rl + tap;
                        ldm4(aF[fm], aS + swz(row*128 + k0b + (sub >> 1)*16));
                    }
                    #pragma unroll
                    for (int nb = 0; nb < 2; nb++) {
                        uint32_t so = swz((n0 + nb*16 + (sub >> 1)*8 + rl)*128 + k0b + (sub & 1)*16);
                        ldm4(bF[nb], bS + tap*8192 + so);
                    }
                    #pragma unroll
                    for (int fm = 0; fm < 2; fm++)
                        #pragma unroll
                        for (int j = 0; j < 4; j++)
                            mma16816(acc[fm][j], aF[fm], &bF[j >> 1][(j & 1)*2]);
                }
            };
            if (isRes) {
                doTap(0);
            } else {
                doTap(0); doTap(1); doTap(2);
            }
        }
        asm volatile("cp.async.wait_all;" ::: "memory");
    }

    // ---- epilogue ----
    const size_t rowBase = (size_t)(nd*128 + hq) * 128;
    #pragma unroll
    for (int fm = 0; fm < 2; fm++) {
        #pragma unroll
        for (int j = 0; j < 4; j++) {
            int c0 = cob*64 + n0 + j*8 + (lane & 3)*2;
            int r0 = m0 + fm*16 + (lane >> 2);
            float b0v = bias[c0], b1v = bias[c0 + 1];
            #pragma unroll
            for (int rr = 0; rr < 2; rr++) {
                int row = r0 + rr*8;
                float v0 = acc[fm][j][rr*2 + 0] + b0v;
                float v1 = acc[fm][j][rr*2 + 1] + b1v;
                if (MODE == 2) {
                    int ohl = row >> 6, ow = row & 63;
                    int oh = hq*2 + ohl;
                    if (ow < OW && oh < OH) {
                        size_t ob = ((size_t)(n*128 + c0)*8 + d)*(OH*OW) + oh*OW + ow;
                        outp[ob] = v0;
                        outp[ob + (size_t)8*(OH*OW)] = v1;
                    }
                } else {
                    if (MODE == 0) {
                        v0 = swish_f(v0) * g_s2[n*128 + c0];
                        v1 = swish_f(v1) * g_s2[n*128 + c0 + 1];
                    } else {
                        v0 = swish_f(v0);
                        v1 = swish_f(v1);
                    }
                    __half h0 = __float2half(v0);
                    __half h1 = __float2half(v1);
                    uint32_t hp = (uint32_t)__half_as_ushort(h1) << 16 |
                                  __half_as_ushort(h0);
                    size_t ob = (rowBase + row)*128 + c0;
                    if (MODE == 0) *(uint32_t*)(g_h1 + ob) = hp;
                    else           *(uint32_t*)(g_h2 + ob) = hp;
                }
            }
        }
    }
}

// ---------------------------------------------------------------------------
extern "C" void kernel_launch(void* const* d_in, const int* in_sizes, int n_in,
                              void* d_out, int out_size)
{
    const float* x       = (const float*)d_in[0];
    const float* embed   = (const float*)d_in[1];
    const float* context = (const float*)d_in[2];
    const float* w20     = (const float*)d_in[3];
    const float* b20     = (const float*)d_in[4];
    const float* w21     = (const float*)d_in[5];
    const float* d1_w    = (const float*)d_in[6];
    const float* d1_b    = (const float*)d_in[7];
    const float* d2_w    = (const float*)d_in[8];
    const float* d2_b    = (const float*)d_in[9];
    const float* res_w   = (const float*)d_in[10];
    const float* res_b   = (const float*)d_in[11];
    const float* down_w  = (const float*)d_in[12];
    const float* down_b  = (const float*)d_in[13];
    float* out = (float*)d_out;

    const int smemP = 2*STAGE_P;          // 83968
    const int smemT = NSTAGE_T*STAGE_T;   // 98304
    cudaFuncSetAttribute(conv_mma<0>, cudaFuncAttributeMaxDynamicSharedMemorySize, smemP);
    cudaFuncSetAttribute(conv_mma<1>, cudaFuncAttributeMaxDynamicSharedMemorySize, smemP);
    cudaFuncSetAttribute(conv_mma<2>, cudaFuncAttributeMaxDynamicSharedMemorySize, smemT);

    s_kernel<<<1, 512>>>(embed, context, d1_w, d1_b, d2_w, d2_b);
    cvt_x_kernel<<<dim3(HH, BB*DD), 256>>>(x);
    wcvt_kernel<<<136, 256>>>(w20, w21, res_w, down_w);

    conv_mma<0><<<dim3(HH, BB*DD, 2), 256, smemP>>>(b20,    nullptr);
    conv_mma<1><<<dim3(HH, BB*DD, 2), 256, smemP>>>(res_b,  nullptr);
    conv_mma<2><<<dim3(32, BB*DD, 2), 256, smemT>>>(down_b, out);
}

// round 8
// speedup vs baseline: 12.0414x; 1.0052x over previous
#include <cuda_runtime.h>
#include <cuda_fp16.h>
#include <cstdint>

// Problem constants
#define BB 4
#define CIN_X 64
#define COUT 128
#define DD 8
#define HH 128
#define WW 128
#define EE 256
#define OH 63
#define OW 63
#define HW (HH*WW)

// ---------------------------------------------------------------------------
// Device-global scratch. Channels-last (NDHWC) fp16 tensors.
// ---------------------------------------------------------------------------
__device__ float g_s1[BB*CIN_X];
__device__ float g_s2[BB*COUT];
__device__ __half g_x[BB*DD*HH*WW*64];            // x (for residual tap)
__device__ __half g_a[BB*DD*HH*WW*64];            // swish(x+s1)
__device__ __half g_h1[(size_t)BB*DD*HH*WW*128];  // after conv20 epi
__device__ __half g_h2[(size_t)BB*DD*HH*WW*128];  // after conv21 epi
// Pre-transposed + pre-swizzled weight tiles: 136 chunks x (128co x 64ci) fp16
// [0,27) conv20 taps; [27,81) conv21 (tap,cihalf); 81 res; [82,136) down
__device__ __half g_w[136*8192];

__device__ __forceinline__ float swish_f(float v) {
    return v / (1.f + __expf(-v));
}

__device__ __forceinline__ uint32_t smem_u32(const void* p) {
    uint32_t a;
    asm("{ .reg .u64 t; cvta.to.shared.u64 t, %1; cvt.u32.u64 %0, t; }" : "=r"(a) : "l"(p));
    return a;
}

__device__ __forceinline__ uint32_t swz(uint32_t off) {
    return off ^ ((off >> 3) & 0x70);
}

__device__ __forceinline__ void cp_async16(uint32_t dst, const void* src, bool valid) {
    int sz = valid ? 16 : 0;
    asm volatile("cp.async.cg.shared.global [%0], [%1], 16, %2;"
                 :: "r"(dst), "l"(src), "r"(sz));
}

__device__ __forceinline__ void ldm4(uint32_t* r, uint32_t addr) {
    asm volatile("ldmatrix.sync.aligned.m8n8.x4.shared.b16 {%0,%1,%2,%3}, [%4];"
                 : "=r"(r[0]), "=r"(r[1]), "=r"(r[2]), "=r"(r[3]) : "r"(addr));
}

__device__ __forceinline__ void mma16816(float* d, const uint32_t* a, const uint32_t* b) {
    asm volatile(
        "mma.sync.aligned.m16n8k16.row.col.f32.f16.f16.f32 "
        "{%0,%1,%2,%3}, {%4,%5,%6,%7}, {%8,%9}, {%0,%1,%2,%3};"
        : "+f"(d[0]), "+f"(d[1]), "+f"(d[2]), "+f"(d[3])
        : "r"(a[0]), "r"(a[1]), "r"(a[2]), "r"(a[3]), "r"(b[0]), "r"(b[1]));
}

// ---------------------------------------------------------------------------
// Kernel 1: s1 = embed @ d1_w + d1_b; s2 = context @ d2_w + d2_b
// ---------------------------------------------------------------------------
__global__ void s_kernel(const float* __restrict__ embed,
                         const float* __restrict__ context,
                         const float* __restrict__ d1w, const float* __restrict__ d1b,
                         const float* __restrict__ d2w, const float* __restrict__ d2b)
{
    int t = threadIdx.x;   // 512 threads
    if (t < BB*CIN_X) {
        int n = t >> 6, c = t & 63;
        float acc = d1b[c];
        #pragma unroll 4
        for (int e = 0; e < EE; e++) acc += embed[n*EE + e] * d1w[e*CIN_X + c];
        g_s1[t] = acc;
    }
    {
        int n = t >> 7, c = t & 127;
        float acc = d2b[c];
        #pragma unroll 4
        for (int e = 0; e < EE; e++) acc += context[n*EE + e] * d2w[e*COUT + c];
        g_s2[t] = acc;
    }
}

// ---------------------------------------------------------------------------
// Kernel 2: NCDHW fp32 x -> channels-last fp16 x and act=swish(x+s1)
// ---------------------------------------------------------------------------
__global__ void __launch_bounds__(256) cvt_x_kernel(const float* __restrict__ x)
{
    __shared__ float sm[64*133];
    const int h  = blockIdx.x;
    const int nd = blockIdx.y;
    const int n  = nd >> 3, d = nd & 7;
    const int tid = threadIdx.x;

    for (int i = tid; i < 64*128; i += 256) {
        int ci = i >> 7, w = i & 127;
        sm[ci*133 + w] = x[((size_t)(n*64 + ci)*8 + d)*HW + h*128 + w];
    }
    __syncthreads();
    size_t base = ((size_t)nd*128 + h) * 128 * 64;
    for (int i = tid; i < 64*128; i += 256) {
        int w = i >> 6, ci = i & 63;
        float v = sm[ci*133 + w];
        float a = swish_f(v + g_s1[n*64 + ci]);
        size_t o = base + (size_t)w*64 + ci;
        g_x[o] = __float2half(v);
        g_a[o] = __float2half(a);
    }
}

// ---------------------------------------------------------------------------
// Kernel 3: weight tiles, transposed (co-row, ci-col), fp16, SW128-swizzled
// ---------------------------------------------------------------------------
__global__ void wcvt_kernel(const float* __restrict__ w20,
                            const float* __restrict__ w21,
                            const float* __restrict__ resw,
                            const float* __restrict__ dwn)
{
    int c = blockIdx.x;     // 0..135
    int tid = threadIdx.x;
    for (int i = tid; i < 8192; i += 256) {
        int co = i >> 6, ci = i & 63;
        float v;
        if (c < 27) {
            v = w20[(co*64 + ci)*27 + c];
        } else if (c < 81) {
            int cc = c - 27; int tap = cc >> 1, half = cc & 1;
            v = w21[(co*128 + half*64 + ci)*27 + tap];
        } else if (c == 81) {
            v = resw[co*64 + ci];
        } else {
            int cc = c - 82; int tap = cc >> 1, half = cc & 1;
            v = dwn[(co*128 + half*64 + ci)*27 + tap];
        }
        uint32_t sw = swz(co*128 + ci*2);
        *(__half*)((char*)g_w + (size_t)c*16384 + sw) = __float2half(v);
    }
}

// ---------------------------------------------------------------------------
// Implicit-GEMM conv, single-pass fp16 mma.sync.
// CTA: 128 threads (4 warps), tile M=128 px x N=64 co (co half via blockIdx.z),
// 2 CTA/SM. Warp tile 32x64 (4M x 1N). Fragments double-buffered across K-slabs.
// MODE 0: conv20. 9 plane-chunks (kd,kh), K=192 each (3 kw taps, 12 K-slabs).
// MODE 1: conv21. 18 plane-half-chunks + 1 residual chunk.
// MODE 2: down. 54 per-tap chunks, M = 2 oh-rows x 64 ow, stride-2 W/H.
// ---------------------------------------------------------------------------
#define STAGE_P   41984   // A 17408 (132 rows x 128B) | B 24576 (3 taps x 64co)
#define STAGE_T   24576   // A 16384 | B 8192
#define NSTAGE_T  4

template<int MODE>
__global__ void __launch_bounds__(128, 2) conv_mma(const float* __restrict__ bias,
                                                   float* __restrict__ outp)
{
    extern __shared__ __align__(1024) char smem[];
    constexpr int NCHUNK = (MODE == 0) ? 9 : (MODE == 1) ? 19 : 54;

    const uint32_t sb = smem_u32(smem);
    const int tid  = threadIdx.x;
    const int wid  = tid >> 5;
    const int lane = tid & 31;
    const int nd = blockIdx.y, n = nd >> 3, d = nd & 7;
    const int hq = blockIdx.x;       // h (MODE 0/1); oh-pair index (MODE 2)
    const int cob = blockIdx.z;      // co half: 0 or 1

    const int m0 = wid * 32;
    const int sub = lane >> 3, rl = lane & 7;

    float acc[2][8][4];
    #pragma unroll
    for (int a = 0; a < 2; a++)
        #pragma unroll
        for (int b = 0; b < 8; b++)
            #pragma unroll
            for (int q = 0; q < 4; q++) acc[a][b][q] = 0.f;

    // double-buffered fragment slots
    uint32_t aF[2][2][4], bF[2][4][4];

    if constexpr (MODE == 2) {
        // ------------------- per-tap scheme -------------------
        auto stage = [&](int c, int buf) {
            uint32_t aS = sb + buf*STAGE_T;
            uint32_t bS = aS + 16384;
            const char* dummy = (const char*)g_w;
            int tap = c >> 1, half = c & 1;
            int kd = tap / 9, kh = (tap / 3) % 3, kw = tap % 3;
            int id = d + kd - 1;
            bool pvd = ((unsigned)id < 8u);
            const char* pl = (const char*)(g_h2 + ((size_t)(n*8 + id)*HW)*128 + half*64);
            #pragma unroll
            for (int t = 0; t < 8; t++) {
                int i = tid + t*128;
                int p = i >> 3, q = i & 7;
                int ohl = p >> 6, ow = p & 63;
                int oh = hq*2 + ohl;
                int iw = 2*ow + kw;
                int ih = oh*2 + kh;
                bool v = pvd && (ow < 63) && (oh < 63);
                size_t off = ((size_t)ih*128 + iw)*256 + q*16;
                cp_async16(aS + swz(p*128 + q*16), v ? pl + off : dummy, v);
            }
            const char* wS = (const char*)g_w + (size_t)(82 + c)*16384 + cob*8192;
            #pragma unroll
            for (int t = 0; t < 4; t++) {
                int i = (tid + t*128)*16;
                cp_async16(bS + i, wS + i, true);
            }
        };

        stage(0, 0);
        asm volatile("cp.async.commit_group;");
        stage(1, 1);
        asm volatile("cp.async.commit_group;");
        stage(2, 2);
        asm volatile("cp.async.commit_group;");

        int bufc = 0;
        for (int c = 0; c < NCHUNK; c++) {
            asm volatile("cp.async.wait_group 2;" ::: "memory");
            __syncthreads();
            int bufn = bufc + 3; if (bufn >= NSTAGE_T) bufn -= NSTAGE_T;
            if (c + 3 < NCHUNK) stage(c + 3, bufn);
            asm volatile("cp.async.commit_group;");

            uint32_t aS = sb + bufc*STAGE_T;
            uint32_t bS = aS + 16384;

            auto loadFrag = [&](int kk, int slot) {
                const int k0b = kk*32;
                #pragma unroll
                for (int fm = 0; fm < 2; fm++) {
                    uint32_t row = m0 + fm*16 + (sub & 1)*8 + rl;
                    ldm4(aF[slot][fm], aS + swz(row*128 + k0b + (sub >> 1)*16));
                }
                #pragma unroll
                for (int nb = 0; nb < 4; nb++) {
                    uint32_t so = swz((nb*16 + (sub >> 1)*8 + rl)*128 + k0b + (sub & 1)*16);
                    ldm4(bF[slot][nb], bS + so);
                }
            };

            loadFrag(0, 0);
            #pragma unroll
            for (int s = 0; s < 4; s++) {
                int cur = s & 1;
                if (s + 1 < 4) loadFrag(s + 1, cur ^ 1);
                #pragma unroll
                for (int fm = 0; fm < 2; fm++)
                    #pragma unroll
                    for (int j = 0; j < 8; j++)
                        mma16816(acc[fm][j], aF[cur][fm], &bF[cur][j >> 1][(j & 1)*2]);
            }
            bufc++; if (bufc >= NSTAGE_T) bufc = 0;
        }
        asm volatile("cp.async.wait_all;" ::: "memory");
    } else {
        // ------------------- plane-chunk scheme -------------------
        auto stage = [&](int c, int buf) {
            uint32_t aS = sb + buf*STAGE_P;
            uint32_t bS = aS + 17408;
            const char* dummy = (const char*)g_w;
            bool isRes = (MODE == 1) && (c == 18);
            if (!isRes) {
                int pc, half, srcStride;
                if (MODE == 0) { pc = c; half = 0; srcStride = 128; }
                else           { pc = c >> 1; half = c & 1; srcStride = 256; }
                int kd = pc / 3, kh = pc % 3;
                int id = d + kd - 1;
                int ih = hq + kh - 1;
                bool pv = ((unsigned)id < 8u) && ((unsigned)ih < 128u);
                const char* src = nullptr;
                if (pv) {
                    size_t pb = ((size_t)((n*8 + id)*128 + ih)) * 128;
                    if (MODE == 0) src = (const char*)(g_a  + pb*64);
                    else           src = (const char*)(g_h1 + pb*128 + half*64);
                }
                // A: rows 0..129 <-> iw -1..128 (zero-filled halo/invalid)
                for (int i = tid; i < 1040; i += 128) {
                    int r = i >> 3, q = i & 7;
                    int iw = r - 1;
                    bool v = pv && ((unsigned)iw < 128u);
                    cp_async16(aS + swz(r*128 + q*16),
                               v ? src + (size_t)iw*srcStride + q*16 : dummy, v);
                }
                // B: 3 kw taps, each 8KB (this CTA's co-half)
                #pragma unroll
                for (int t = 0; t < 12; t++) {
                    int i = tid + t*128;      // 1536 16B-units
                    int kw = i >> 9, j = i & 511;
                    int wchunk = (MODE == 0) ? (pc*3 + kw)
                                             : 27 + ((pc*3 + kw)*2 + half);
                    const char* wS = (const char*)g_w + (size_t)wchunk*16384 + cob*8192;
                    cp_async16(bS + i*16, wS + j*16, true);
                }
            } else {
                // residual 1x1x1 tap
                const char* src = (const char*)(g_x + ((size_t)(nd*128 + hq))*128*64);
                #pragma unroll
                for (int t = 0; t < 8; t++) {
                    int i = tid + t*128;
                    int r = i >> 3, q = i & 7;
                    cp_async16(aS + swz(r*128 + q*16), src + (size_t)r*128 + q*16, true);
                }
                const char* wS = (const char*)g_w + (size_t)81*16384 + cob*8192;
                #pragma unroll
                for (int t = 0; t < 4; t++) {
                    int i = (tid + t*128)*16;
                    cp_async16(bS + i, wS + i, true);
                }
            }
        };

        stage(0, 0);
        asm volatile("cp.async.commit_group;");

        for (int c = 0; c < NCHUNK; c++) {
            asm volatile("cp.async.wait_group 0;" ::: "memory");
            __syncthreads();
            if (c + 1 < NCHUNK) stage(c + 1, (c + 1) & 1);
            asm volatile("cp.async.commit_group;");

            uint32_t aS = sb + (c & 1)*STAGE_P;
            uint32_t bS = aS + 17408;
            bool isRes = (MODE == 1) && (c == 18);

            auto loadFrag = [&](int tap, int kk, int slot) {
                const int k0b = kk*32;
                #pragma unroll
                for (int fm = 0; fm < 2; fm++) {
                    uint32_t row = m0 + fm*16 + (sub & 1)*8 + rl + tap;
                    ldm4(aF[slot][fm], aS + swz(row*128 + k0b + (sub >> 1)*16));
                }
                #pragma unroll
                for (int nb = 0; nb < 4; nb++) {
                    uint32_t so = swz((nb*16 + (sub >> 1)*8 + rl)*128 + k0b + (sub & 1)*16);
                    ldm4(bF[slot][nb], bS + tap*8192 + so);
                }
            };
            auto mmaSlab = [&](int cur) {
                #pragma unroll
                for (int fm = 0; fm < 2; fm++)
                    #pragma unroll
                    for (int j = 0; j < 8; j++)
                        mma16816(acc[fm][j], aF[cur][fm], &bF[cur][j >> 1][(j & 1)*2]);
            };

            if (isRes) {
                loadFrag(0, 0, 0);
                #pragma unroll
                for (int s = 0; s < 4; s++) {
                    int cur = s & 1;
                    if (s + 1 < 4) loadFrag(0, s + 1, cur ^ 1);
                    mmaSlab(cur);
                }
            } else {
                loadFrag(0, 0, 0);
                #pragma unroll
                for (int s = 0; s < 12; s++) {
                    int cur = s & 1;
                    if (s + 1 < 12) loadFrag((s + 1) >> 2, (s + 1) & 3, cur ^ 1);
                    mmaSlab(cur);
                }
            }
        }
        asm volatile("cp.async.wait_all;" ::: "memory");
    }

    // ---- epilogue ----
    const size_t rowBase = (size_t)(nd*128 + hq) * 128;
    #pragma unroll
    for (int fm = 0; fm < 2; fm++) {
        #pragma unroll
        for (int j = 0; j < 8; j++) {
            int c0 = cob*64 + j*8 + (lane & 3)*2;
            int r0 = m0 + fm*16 + (lane >> 2);
            float b0v = bias[c0], b1v = bias[c0 + 1];
            #pragma unroll
            for (int rr = 0; rr < 2; rr++) {
                int row = r0 + rr*8;
                float v0 = acc[fm][j][rr*2 + 0] + b0v;
                float v1 = acc[fm][j][rr*2 + 1] + b1v;
                if (MODE == 2) {
                    int ohl = row >> 6, ow = row & 63;
                    int oh = hq*2 + ohl;
                    if (ow < OW && oh < OH) {
                        size_t ob = ((size_t)(n*128 + c0)*8 + d)*(OH*OW) + oh*OW + ow;
                        outp[ob] = v0;
                        outp[ob + (size_t)8*(OH*OW)] = v1;
                    }
                } else {
                    if (MODE == 0) {
                        v0 = swish_f(v0) * g_s2[n*128 + c0];
                        v1 = swish_f(v1) * g_s2[n*128 + c0 + 1];
                    } else {
                        v0 = swish_f(v0);
                        v1 = swish_f(v1);
                    }
                    __half h0 = __float2half(v0);
                    __half h1 = __float2half(v1);
                    uint32_t hp = (uint32_t)__half_as_ushort(h1) << 16 |
                                  __half_as_ushort(h0);
                    size_t ob = (rowBase + row)*128 + c0;
                    if (MODE == 0) *(uint32_t*)(g_h1 + ob) = hp;
                    else           *(uint32_t*)(g_h2 + ob) = hp;
                }
            }
        }
    }
}

// ---------------------------------------------------------------------------
extern "C" void kernel_launch(void* const* d_in, const int* in_sizes, int n_in,
                              void* d_out, int out_size)
{
    const float* x       = (const float*)d_in[0];
    const float* embed   = (const float*)d_in[1];
    const float* context = (const float*)d_in[2];
    const float* w20     = (const float*)d_in[3];
    const float* b20     = (const float*)d_in[4];
    const float* w21     = (const float*)d_in[5];
    const float* d1_w    = (const float*)d_in[6];
    const float* d1_b    = (const float*)d_in[7];
    const float* d2_w    = (const float*)d_in[8];
    const float* d2_b    = (const float*)d_in[9];
    const float* res_w   = (const float*)d_in[10];
    const float* res_b   = (const float*)d_in[11];
    const float* down_w  = (const float*)d_in[12];
    const float* down_b  = (const float*)d_in[13];
    float* out = (float*)d_out;

    const int smemP = 2*STAGE_P;          // 83968
    const int smemT = NSTAGE_T*STAGE_T;   // 98304
    cudaFuncSetAttribute(conv_mma<0>, cudaFuncAttributeMaxDynamicSharedMemorySize, smemP);
    cudaFuncSetAttribute(conv_mma<1>, cudaFuncAttributeMaxDynamicSharedMemorySize, smemP);
    cudaFuncSetAttribute(conv_mma<2>, cudaFuncAttributeMaxDynamicSharedMemorySize, smemT);

    s_kernel<<<1, 512>>>(embed, context, d1_w, d1_b, d2_w, d2_b);
    cvt_x_kernel<<<dim3(HH, BB*DD), 256>>>(x);
    wcvt_kernel<<<136, 256>>>(w20, w21, res_w, down_w);

    conv_mma<0><<<dim3(HH, BB*DD, 2), 128, smemP>>>(b20,    nullptr);
    conv_mma<1><<<dim3(HH, BB*DD, 2), 128, smemP>>>(res_b,  nullptr);
    conv_mma<2><<<dim3(32, BB*DD, 2), 128, smemT>>>(down_b, out);
}